// round 1
// baseline (speedup 1.0000x reference)
#include <cuda_runtime.h>

#define NB 8
#define CD 256
#define LD 6400
#define NHEADS 8
#define HC 32

// Scratch (device globals -- no allocation allowed)
__device__ float g_Q[NB * CD * LD];
__device__ float g_K[NB * CD * LD];
__device__ float g_V[NB * CD * LD];
__device__ float g_ATT[NB * CD * LD];
__device__ float g_CTX[NB * NHEADS * HC * HC];

// ---------------------------------------------------------------------------
// SGEMM: Y[n, m, l] = sum_k W[m,k] * X[n,k,l] + bias[m] (+ resid[n,m,l])
// M=256, K=256, N(L)=6400 per batch. Tiles: BM=128, BN=128, BK=16.
// 256 threads, 8x8 per-thread microtile.
// ---------------------------------------------------------------------------
__global__ __launch_bounds__(256) void sgemm_kernel(
    const float* __restrict__ X, const float* __restrict__ W,
    const float* __restrict__ bias, const float* __restrict__ resid,
    float* __restrict__ Y)
{
    const int n  = blockIdx.z;
    const int m0 = blockIdx.y * 128;
    const int l0 = blockIdx.x * 128;
    const float* Xn = X + (size_t)n * CD * LD;
    float* Yn = Y + (size_t)n * CD * LD;

    __shared__ float As[16][128];   // As[k][m]
    __shared__ float Bs[16][128];   // Bs[k][l]

    const int tid = threadIdx.x;
    const int tr  = tid >> 4;   // 0..15
    const int tc  = tid & 15;   // 0..15

    float acc[8][8];
#pragma unroll
    for (int i = 0; i < 8; i++)
#pragma unroll
        for (int j = 0; j < 8; j++) acc[i][j] = 0.0f;

    for (int kt = 0; kt < CD; kt += 16) {
        // Load A tile (128 rows x 16 k) transposed into As[k][m]
#pragma unroll
        for (int s = 0; s < 2; ++s) {
            int f   = tid + s * 256;      // float4 index 0..511
            int row = f >> 2;
            int kq  = f & 3;
            float4 v = *(const float4*)(W + (size_t)(m0 + row) * CD + kt + kq * 4);
            As[kq * 4 + 0][row] = v.x;
            As[kq * 4 + 1][row] = v.y;
            As[kq * 4 + 2][row] = v.z;
            As[kq * 4 + 3][row] = v.w;
        }
        // Load B tile (16 k x 128 l)
#pragma unroll
        for (int s = 0; s < 2; ++s) {
            int f   = tid + s * 256;      // float4 index 0..511
            int row = f >> 5;
            int lq  = f & 31;
            float4 v = *(const float4*)(Xn + (size_t)(kt + row) * LD + l0 + lq * 4);
            *(float4*)&Bs[row][lq * 4] = v;
        }
        __syncthreads();

#pragma unroll
        for (int k = 0; k < 16; ++k) {
            float4 a0 = *(const float4*)&As[k][tr * 8];
            float4 a1 = *(const float4*)&As[k][tr * 8 + 4];
            float4 b0 = *(const float4*)&Bs[k][tc * 8];
            float4 b1 = *(const float4*)&Bs[k][tc * 8 + 4];
            float a[8] = {a0.x, a0.y, a0.z, a0.w, a1.x, a1.y, a1.z, a1.w};
            float b[8] = {b0.x, b0.y, b0.z, b0.w, b1.x, b1.y, b1.z, b1.w};
#pragma unroll
            for (int i = 0; i < 8; i++)
#pragma unroll
                for (int j = 0; j < 8; j++)
                    acc[i][j] += a[i] * b[j];
        }
        __syncthreads();
    }

    // Epilogue: bias (+ residual), vectorized stores
#pragma unroll
    for (int i = 0; i < 8; i++) {
        int m = m0 + tr * 8 + i;
        float bv = bias[m];
        size_t rowbase = (size_t)m * LD + l0 + tc * 8;
#pragma unroll
        for (int jq = 0; jq < 2; jq++) {
            float4 o;
            o.x = acc[i][jq * 4 + 0] + bv;
            o.y = acc[i][jq * 4 + 1] + bv;
            o.z = acc[i][jq * 4 + 2] + bv;
            o.w = acc[i][jq * 4 + 3] + bv;
            if (resid) {
                float4 r = *(const float4*)(resid + (size_t)n * CD * LD + rowbase + jq * 4);
                o.x += r.x; o.y += r.y; o.z += r.z; o.w += r.w;
            }
            *(float4*)(Yn + rowbase + jq * 4) = o;
        }
    }
}

// ---------------------------------------------------------------------------
// Softmax over L=6400 per (n, channel) row. One block per row, row in smem.
// ---------------------------------------------------------------------------
__global__ __launch_bounds__(256) void softmax_L_kernel(float* __restrict__ D)
{
    __shared__ float buf[LD];
    __shared__ float red[256];
    float* row = D + (size_t)blockIdx.x * LD;
    const int tid = threadIdx.x;

    float mx = -1e30f;
    for (int i = tid; i < LD; i += 256) {
        float v = row[i];
        buf[i] = v;
        mx = fmaxf(mx, v);
    }
    red[tid] = mx;
    __syncthreads();
    for (int s = 128; s > 0; s >>= 1) {
        if (tid < s) red[tid] = fmaxf(red[tid], red[tid + s]);
        __syncthreads();
    }
    mx = red[0];
    __syncthreads();

    float sm = 0.0f;
    for (int i = tid; i < LD; i += 256) {
        float e = __expf(buf[i] - mx);
        buf[i] = e;
        sm += e;
    }
    red[tid] = sm;
    __syncthreads();
    for (int s = 128; s > 0; s >>= 1) {
        if (tid < s) red[tid] += red[tid + s];
        __syncthreads();
    }
    float inv = 1.0f / red[0];
    for (int i = tid; i < LD; i += 256) row[i] = buf[i] * inv;
}

// ---------------------------------------------------------------------------
// Softmax over the 32 in-head channels per (n, h, l). Register-resident.
// grid (L/128, HEADS, NB), 128 threads.
// ---------------------------------------------------------------------------
__global__ __launch_bounds__(128) void softmax_C_kernel(float* __restrict__ Q)
{
    const int l = blockIdx.x * 128 + threadIdx.x;
    const size_t base = (((size_t)blockIdx.z * NHEADS + blockIdx.y) * HC) * LD + l;
    float v[HC];
    float mx = -1e30f;
#pragma unroll
    for (int c = 0; c < HC; c++) {
        v[c] = Q[base + (size_t)c * LD];
        mx = fmaxf(mx, v[c]);
    }
    float s = 0.0f;
#pragma unroll
    for (int c = 0; c < HC; c++) {
        v[c] = __expf(v[c] - mx);
        s += v[c];
    }
    float inv = 1.0f / s;
#pragma unroll
    for (int c = 0; c < HC; c++) Q[base + (size_t)c * LD] = v[c] * inv;
}

__global__ void zero_ctx_kernel()
{
    g_CTX[blockIdx.x * 256 + threadIdx.x] = 0.0f;
}

// ---------------------------------------------------------------------------
// context[n,h,kc,vc] = sum_l K[n,h,kc,l] * V[n,h,vc,l]
// grid (10 L-chunks of 640, HEADS, NB), 256 threads, atomicAdd accumulate.
// ---------------------------------------------------------------------------
__global__ __launch_bounds__(256) void context_kernel()
{
    __shared__ float sk[32][129];
    __shared__ float sv[32][129];
    const int n = blockIdx.z, h = blockIdx.y;
    const size_t base = (((size_t)n * NHEADS + h) * HC) * LD;
    const int tid = threadIdx.x;
    const int kc = tid >> 3;
    const int vg = (tid & 7) * 4;

    float acc0 = 0.f, acc1 = 0.f, acc2 = 0.f, acc3 = 0.f;

    for (int t = 0; t < 5; ++t) {
        const int l0 = blockIdx.x * 640 + t * 128;
#pragma unroll
        for (int s = 0; s < 16; s++) {
            int idx = tid + s * 256;
            int c = idx >> 7, l = idx & 127;
            sk[c][l] = g_K[base + (size_t)c * LD + l0 + l];
            sv[c][l] = g_V[base + (size_t)c * LD + l0 + l];
        }
        __syncthreads();
#pragma unroll 4
        for (int l = 0; l < 128; l++) {
            float a = sk[kc][l];
            acc0 += a * sv[vg + 0][l];
            acc1 += a * sv[vg + 1][l];
            acc2 += a * sv[vg + 2][l];
            acc3 += a * sv[vg + 3][l];
        }
        __syncthreads();
    }
    const size_t cb = (((size_t)n * NHEADS + h) * HC + kc) * HC + vg;
    atomicAdd(&g_CTX[cb + 0], acc0);
    atomicAdd(&g_CTX[cb + 1], acc1);
    atomicAdd(&g_CTX[cb + 2], acc2);
    atomicAdd(&g_CTX[cb + 3], acc3);
}

// ---------------------------------------------------------------------------
// attended[n,h,vc,l] = sum_kc ctx[n,h,kc,vc] * q[n,h,kc,l]
// grid (L/128, HEADS, NB), 128 threads (one column l per thread).
// ---------------------------------------------------------------------------
__global__ __launch_bounds__(128) void attend_kernel()
{
    __shared__ float4 sctx[32][8];   // ctx[kc][vc packed 4]
    const int n = blockIdx.z, h = blockIdx.y;
    const int tid = threadIdx.x;
    {
        const float4* C = (const float4*)(g_CTX + (((size_t)n * NHEADS + h) * HC) * HC);
#pragma unroll
        for (int s = 0; s < 2; s++) {
            int idx = tid + s * 128;  // 0..255 float4s
            sctx[idx >> 3][idx & 7] = C[idx];
        }
    }
    __syncthreads();

    const int l = blockIdx.x * 128 + tid;
    const size_t base = (((size_t)n * NHEADS + h) * HC) * LD + l;

    float q[HC];
#pragma unroll
    for (int c = 0; c < HC; c++) q[c] = g_Q[base + (size_t)c * LD];

    float acc[HC];
#pragma unroll
    for (int v = 0; v < HC; v++) acc[v] = 0.0f;

#pragma unroll
    for (int kc = 0; kc < HC; kc++) {
        float a = q[kc];
#pragma unroll
        for (int vq = 0; vq < 8; vq++) {
            float4 c4 = sctx[kc][vq];
            acc[vq * 4 + 0] += a * c4.x;
            acc[vq * 4 + 1] += a * c4.y;
            acc[vq * 4 + 2] += a * c4.z;
            acc[vq * 4 + 3] += a * c4.w;
        }
    }
#pragma unroll
    for (int v = 0; v < HC; v++) g_ATT[base + (size_t)v * LD] = acc[v];
}

// ---------------------------------------------------------------------------
extern "C" void kernel_launch(void* const* d_in, const int* in_sizes, int n_in,
                              void* d_out, int out_size)
{
    const float* qf = (const float*)d_in[0];
    const float* kf = (const float*)d_in[1];
    const float* vf = (const float*)d_in[2];
    const float* Wq = (const float*)d_in[3];
    const float* bq = (const float*)d_in[4];
    const float* Wk = (const float*)d_in[5];
    const float* bk = (const float*)d_in[6];
    const float* Wv = (const float*)d_in[7];
    const float* bv = (const float*)d_in[8];
    const float* Wr = (const float*)d_in[9];
    const float* br = (const float*)d_in[10];
    float* out = (float*)d_out;

    float *Q, *K, *V, *ATT;
    cudaGetSymbolAddress((void**)&Q,   g_Q);
    cudaGetSymbolAddress((void**)&K,   g_K);
    cudaGetSymbolAddress((void**)&V,   g_V);
    cudaGetSymbolAddress((void**)&ATT, g_ATT);

    dim3 gemm_grid(LD / 128, CD / 128, NB);     // (50, 2, 8)
    sgemm_kernel<<<gemm_grid, 256>>>(qf, Wq, bq, nullptr, Q);
    sgemm_kernel<<<gemm_grid, 256>>>(kf, Wk, bk, nullptr, K);
    sgemm_kernel<<<gemm_grid, 256>>>(vf, Wv, bv, nullptr, V);

    softmax_L_kernel<<<NB * CD, 256>>>(K);
    softmax_C_kernel<<<dim3(LD / 128, NHEADS, NB), 128>>>(Q);

    zero_ctx_kernel<<<(NB * NHEADS * HC * HC) / 256, 256>>>();
    context_kernel<<<dim3(10, NHEADS, NB), 256>>>();
    attend_kernel<<<dim3(LD / 128, NHEADS, NB), 128>>>();

    sgemm_kernel<<<gemm_grid, 256>>>(ATT, Wr, br, qf, out);
}

// round 3
// speedup vs baseline: 1.7607x; 1.7607x over previous
#include <cuda_runtime.h>
#include <cuda_bf16.h>
#include <cstdint>

#define NB 8
#define CD 256
#define LD 6400
#define NHEADS 8
#define HC 32

// Scratch (device globals -- no allocation allowed)
__device__ float g_Q[NB * CD * LD];
__device__ float g_K[NB * CD * LD];
__device__ float g_V[NB * CD * LD];
__device__ float g_ATT[NB * CD * LD];
__device__ float g_CTX[NB * NHEADS * HC * HC];

// ---------------------------------------------------------------------------
// mma.sync / ldmatrix helpers (baseline PTX, works on compute_103)
// ---------------------------------------------------------------------------
__device__ __forceinline__ uint32_t smem_u32(const void* p) {
    uint32_t a;
    asm("{ .reg .u64 t; cvta.to.shared.u64 t, %1; cvt.u32.u64 %0, t; }"
        : "=r"(a) : "l"(p));
    return a;
}

__device__ __forceinline__ void ldsm4(uint32_t* r, uint32_t addr) {
    asm volatile("ldmatrix.sync.aligned.m8n8.x4.shared.b16 {%0,%1,%2,%3}, [%4];"
                 : "=r"(r[0]), "=r"(r[1]), "=r"(r[2]), "=r"(r[3]) : "r"(addr));
}
__device__ __forceinline__ void ldsm2t(uint32_t* r, uint32_t addr) {
    asm volatile("ldmatrix.sync.aligned.m8n8.x2.trans.shared.b16 {%0,%1}, [%2];"
                 : "=r"(r[0]), "=r"(r[1]) : "r"(addr));
}

__device__ __forceinline__ void mma16816(float* c, const uint32_t* a, const uint32_t* b) {
    asm volatile(
        "mma.sync.aligned.m16n8k16.row.col.f32.bf16.bf16.f32 "
        "{%0,%1,%2,%3}, {%4,%5,%6,%7}, {%8,%9}, {%0,%1,%2,%3};"
        : "+f"(c[0]), "+f"(c[1]), "+f"(c[2]), "+f"(c[3])
        : "r"(a[0]), "r"(a[1]), "r"(a[2]), "r"(a[3]), "r"(b[0]), "r"(b[1]));
}

// ---------------------------------------------------------------------------
// HMMA GEMM: Y[n, m, l] = sum_k W[m,k] * X[n,k,l] + bias[m] (+ resid)
// Block tile 128(m) x 128(l), BK=32, 8 warps (warp tile 32x64).
// bf16 hi/lo split: acc += Ahi*Bhi + Ahi*Blo + Alo*Bhi (fp32 accum in regs)
// ---------------------------------------------------------------------------
#define SA 40    // bf16 stride of A smem rows (80B -> conflict-free ldmatrix)
#define SB 136   // bf16 stride of B smem rows (272B -> conflict-free ldmatrix)

__global__ __launch_bounds__(256, 2) void hmma_gemm_kernel(
    const float* __restrict__ X, const float* __restrict__ W,
    const float* __restrict__ bias, const float* __restrict__ resid,
    float* __restrict__ Y)
{
    __shared__ __align__(16) __nv_bfloat16 As_hi[128 * SA];
    __shared__ __align__(16) __nv_bfloat16 As_lo[128 * SA];
    __shared__ __align__(16) __nv_bfloat16 Bs_hi[32 * SB];
    __shared__ __align__(16) __nv_bfloat16 Bs_lo[32 * SB];

    const int tid  = threadIdx.x;
    const int wid  = tid >> 5;
    const int lane = tid & 31;
    const int l0   = blockIdx.x * 128;
    const int m0   = blockIdx.y * 128;
    const int nb   = blockIdx.z;

    const int m0w = (wid & 3) * 32;   // warp m offset in block
    const int n0w = (wid >> 2) * 64;  // warp n offset in block

    const float* Xn = X + (size_t)nb * CD * LD;
    float* Yn = Y + (size_t)nb * CD * LD;
    const float* Rn = resid ? resid + (size_t)nb * CD * LD : nullptr;

    float acc[2][8][4];
#pragma unroll
    for (int i = 0; i < 2; i++)
#pragma unroll
        for (int j = 0; j < 8; j++)
#pragma unroll
            for (int e = 0; e < 4; e++) acc[i][j][e] = 0.0f;

    // Precompute ldmatrix lane addresses
    // A (x4): tile = lane/8; row-in-tile = lane%8
    //   m = m0w + (tile&1)*8 + row ; k = (tile>>1)*8
    const int a_tile = lane >> 3;
    const int a_row  = m0w + ((a_tile & 1) << 3) + (lane & 7);
    const int a_koff = (a_tile >> 1) << 3;
    const uint32_t aAddrHi0 = smem_u32(&As_hi[a_row * SA + a_koff]);
    const uint32_t aAddrLo0 = smem_u32(&As_lo[a_row * SA + a_koff]);
    // B (x2.trans): lane 0-15 -> k row; n offset per jn
    const int b_k = lane & 15;
    const uint32_t bAddrHi0 = smem_u32(&Bs_hi[b_k * SB + n0w]);
    const uint32_t bAddrLo0 = smem_u32(&Bs_lo[b_k * SB + n0w]);

    const float4* W4 = (const float4*)W;
    const float4* X4 = (const float4*)Xn;

    for (int c = 0; c < 8; ++c) {
        // ---- global loads for this chunk into regs (overlap w/ prev compute)
        float4 av[4], bv4[4];
#pragma unroll
        for (int i = 0; i < 4; ++i) {
            int f4  = tid + i * 256;      // 0..1023
            int row = f4 >> 3;            // 0..127
            int kq  = f4 & 7;             // float4 within 32-k chunk
            av[i] = W4[(size_t)(m0 + row) * 64 + c * 8 + kq];
        }
#pragma unroll
        for (int i = 0; i < 4; ++i) {
            int f4 = tid + i * 256;       // 0..1023
            int k  = f4 >> 5;             // 0..31
            int lq = f4 & 31;
            bv4[i] = X4[(size_t)(c * 32 + k) * (LD / 4) + (l0 >> 2) + lq];
        }

        __syncthreads();   // previous chunk's compute done, smem reusable

        // ---- convert + store to smem
#pragma unroll
        for (int i = 0; i < 4; ++i) {
            int f4  = tid + i * 256;
            int row = f4 >> 3;
            int kq  = f4 & 7;
            union { __nv_bfloat16 b[4]; unsigned long long u; } uh, ul;
            float vv[4] = {av[i].x, av[i].y, av[i].z, av[i].w};
#pragma unroll
            for (int e = 0; e < 4; ++e) {
                __nv_bfloat16 h = __float2bfloat16(vv[e]);
                uh.b[e] = h;
                ul.b[e] = __float2bfloat16(vv[e] - __bfloat162float(h));
            }
            *(unsigned long long*)&As_hi[row * SA + kq * 4] = uh.u;
            *(unsigned long long*)&As_lo[row * SA + kq * 4] = ul.u;
        }
#pragma unroll
        for (int i = 0; i < 4; ++i) {
            int f4 = tid + i * 256;
            int k  = f4 >> 5;
            int lq = f4 & 31;
            union { __nv_bfloat16 b[4]; unsigned long long u; } uh, ul;
            float vv[4] = {bv4[i].x, bv4[i].y, bv4[i].z, bv4[i].w};
#pragma unroll
            for (int e = 0; e < 4; ++e) {
                __nv_bfloat16 h = __float2bfloat16(vv[e]);
                uh.b[e] = h;
                ul.b[e] = __float2bfloat16(vv[e] - __bfloat162float(h));
            }
            *(unsigned long long*)&Bs_hi[k * SB + lq * 4] = uh.u;
            *(unsigned long long*)&Bs_lo[k * SB + lq * 4] = ul.u;
        }
        __syncthreads();

        // ---- compute: 2 k16-steps
#pragma unroll
        for (int ks = 0; ks < 2; ++ks) {
            uint32_t a_hi[2][4], a_lo[2][4];
#pragma unroll
            for (int im = 0; im < 2; ++im) {
                // byte offset: im*16 rows, ks*16 k
                uint32_t ofs = (uint32_t)(im * 16 * SA + ks * 16) * 2;
                ldsm4(a_hi[im], aAddrHi0 + ofs);
                ldsm4(a_lo[im], aAddrLo0 + ofs);
            }
#pragma unroll
            for (int jn = 0; jn < 8; ++jn) {
                uint32_t b_hi[2], b_lo[2];
                uint32_t ofs = (uint32_t)(ks * 16 * SB + jn * 8) * 2;
                ldsm2t(b_hi, bAddrHi0 + ofs);
                ldsm2t(b_lo, bAddrLo0 + ofs);
#pragma unroll
                for (int im = 0; im < 2; ++im) {
                    mma16816(acc[im][jn], a_hi[im], b_hi);
                    mma16816(acc[im][jn], a_hi[im], b_lo);
                    mma16816(acc[im][jn], a_lo[im], b_hi);
                }
            }
        }
    }

    // ---- epilogue: regs -> global, + bias (+ residual)
    const int qr = lane >> 2;        // 0..7
    const int qc = (lane & 3) * 2;   // 0,2,4,6
#pragma unroll
    for (int im = 0; im < 2; ++im) {
        int mA = m0 + m0w + im * 16 + qr;
        int mB = mA + 8;
        float bA = bias[mA];
        float bB = bias[mB];
#pragma unroll
        for (int jn = 0; jn < 8; ++jn) {
            int n = l0 + n0w + jn * 8 + qc;
            size_t gA = (size_t)mA * LD + n;
            size_t gB = (size_t)mB * LD + n;
            float o0 = acc[im][jn][0] + bA;
            float o1 = acc[im][jn][1] + bA;
            float o2 = acc[im][jn][2] + bB;
            float o3 = acc[im][jn][3] + bB;
            if (Rn) {
                float2 rA = *(const float2*)(Rn + gA);
                float2 rB = *(const float2*)(Rn + gB);
                o0 += rA.x; o1 += rA.y; o2 += rB.x; o3 += rB.y;
            }
            float2 vA = {o0, o1};
            float2 vB = {o2, o3};
            *(float2*)(Yn + gA) = vA;
            *(float2*)(Yn + gB) = vB;
        }
    }
}

// ---------------------------------------------------------------------------
// Softmax over L=6400 per (n, channel) row. One block per row, row in smem.
// ---------------------------------------------------------------------------
__global__ __launch_bounds__(256) void softmax_L_kernel(float* __restrict__ D)
{
    __shared__ float buf[LD];
    __shared__ float red[256];
    float* row = D + (size_t)blockIdx.x * LD;
    const int tid = threadIdx.x;

    float mx = -1e30f;
    for (int i = tid; i < LD; i += 256) {
        float v = row[i];
        buf[i] = v;
        mx = fmaxf(mx, v);
    }
    red[tid] = mx;
    __syncthreads();
    for (int s = 128; s > 0; s >>= 1) {
        if (tid < s) red[tid] = fmaxf(red[tid], red[tid + s]);
        __syncthreads();
    }
    mx = red[0];
    __syncthreads();

    float sm = 0.0f;
    for (int i = tid; i < LD; i += 256) {
        float e = __expf(buf[i] - mx);
        buf[i] = e;
        sm += e;
    }
    red[tid] = sm;
    __syncthreads();
    for (int s = 128; s > 0; s >>= 1) {
        if (tid < s) red[tid] += red[tid + s];
        __syncthreads();
    }
    float inv = 1.0f / red[0];
    for (int i = tid; i < LD; i += 256) row[i] = buf[i] * inv;
}

// ---------------------------------------------------------------------------
// Softmax over the 32 in-head channels per (n, h, l). Register-resident.
// ---------------------------------------------------------------------------
__global__ __launch_bounds__(128) void softmax_C_kernel(float* __restrict__ Q)
{
    const int l = blockIdx.x * 128 + threadIdx.x;
    const size_t base = (((size_t)blockIdx.z * NHEADS + blockIdx.y) * HC) * LD + l;
    float v[HC];
    float mx = -1e30f;
#pragma unroll
    for (int c = 0; c < HC; c++) {
        v[c] = Q[base + (size_t)c * LD];
        mx = fmaxf(mx, v[c]);
    }
    float s = 0.0f;
#pragma unroll
    for (int c = 0; c < HC; c++) {
        v[c] = __expf(v[c] - mx);
        s += v[c];
    }
    float inv = 1.0f / s;
#pragma unroll
    for (int c = 0; c < HC; c++) Q[base + (size_t)c * LD] = v[c] * inv;
}

__global__ void zero_ctx_kernel()
{
    g_CTX[blockIdx.x * 256 + threadIdx.x] = 0.0f;
}

// ---------------------------------------------------------------------------
// context[n,h,kc,vc] = sum_l K[n,h,kc,l] * V[n,h,vc,l]
// ---------------------------------------------------------------------------
__global__ __launch_bounds__(256) void context_kernel()
{
    __shared__ float sk[32][129];
    __shared__ float sv[32][129];
    const int n = blockIdx.z, h = blockIdx.y;
    const size_t base = (((size_t)n * NHEADS + h) * HC) * LD;
    const int tid = threadIdx.x;
    const int kc = tid >> 3;
    const int vg = (tid & 7) * 4;

    float acc0 = 0.f, acc1 = 0.f, acc2 = 0.f, acc3 = 0.f;

    for (int t = 0; t < 5; ++t) {
        const int l0 = blockIdx.x * 640 + t * 128;
#pragma unroll
        for (int s = 0; s < 16; s++) {
            int idx = tid + s * 256;
            int c = idx >> 7, l = idx & 127;
            sk[c][l] = g_K[base + (size_t)c * LD + l0 + l];
            sv[c][l] = g_V[base + (size_t)c * LD + l0 + l];
        }
        __syncthreads();
#pragma unroll 4
        for (int l = 0; l < 128; l++) {
            float a = sk[kc][l];
            acc0 += a * sv[vg + 0][l];
            acc1 += a * sv[vg + 1][l];
            acc2 += a * sv[vg + 2][l];
            acc3 += a * sv[vg + 3][l];
        }
        __syncthreads();
    }
    const size_t cb = (((size_t)n * NHEADS + h) * HC + kc) * HC + vg;
    atomicAdd(&g_CTX[cb + 0], acc0);
    atomicAdd(&g_CTX[cb + 1], acc1);
    atomicAdd(&g_CTX[cb + 2], acc2);
    atomicAdd(&g_CTX[cb + 3], acc3);
}

// ---------------------------------------------------------------------------
// attended[n,h,vc,l] = sum_kc ctx[n,h,kc,vc] * q[n,h,kc,l]
// ---------------------------------------------------------------------------
__global__ __launch_bounds__(128) void attend_kernel()
{
    __shared__ float4 sctx[32][8];
    const int n = blockIdx.z, h = blockIdx.y;
    const int tid = threadIdx.x;
    {
        const float4* C = (const float4*)(g_CTX + (((size_t)n * NHEADS + h) * HC) * HC);
#pragma unroll
        for (int s = 0; s < 2; s++) {
            int idx = tid + s * 128;
            sctx[idx >> 3][idx & 7] = C[idx];
        }
    }
    __syncthreads();

    const int l = blockIdx.x * 128 + tid;
    const size_t base = (((size_t)n * NHEADS + h) * HC) * LD + l;

    float q[HC];
#pragma unroll
    for (int c = 0; c < HC; c++) q[c] = g_Q[base + (size_t)c * LD];

    float acc[HC];
#pragma unroll
    for (int v = 0; v < HC; v++) acc[v] = 0.0f;

#pragma unroll
    for (int kc = 0; kc < HC; kc++) {
        float a = q[kc];
#pragma unroll
        for (int vq = 0; vq < 8; vq++) {
            float4 c4 = sctx[kc][vq];
            acc[vq * 4 + 0] += a * c4.x;
            acc[vq * 4 + 1] += a * c4.y;
            acc[vq * 4 + 2] += a * c4.z;
            acc[vq * 4 + 3] += a * c4.w;
        }
    }
#pragma unroll
    for (int v = 0; v < HC; v++) g_ATT[base + (size_t)v * LD] = acc[v];
}

// ---------------------------------------------------------------------------
extern "C" void kernel_launch(void* const* d_in, const int* in_sizes, int n_in,
                              void* d_out, int out_size)
{
    const float* qf = (const float*)d_in[0];
    const float* kf = (const float*)d_in[1];
    const float* vf = (const float*)d_in[2];
    const float* Wq = (const float*)d_in[3];
    const float* bq = (const float*)d_in[4];
    const float* Wk = (const float*)d_in[5];
    const float* bk = (const float*)d_in[6];
    const float* Wv = (const float*)d_in[7];
    const float* bv = (const float*)d_in[8];
    const float* Wr = (const float*)d_in[9];
    const float* br = (const float*)d_in[10];
    float* out = (float*)d_out;

    float *Q, *K, *V, *ATT;
    cudaGetSymbolAddress((void**)&Q,   g_Q);
    cudaGetSymbolAddress((void**)&K,   g_K);
    cudaGetSymbolAddress((void**)&V,   g_V);
    cudaGetSymbolAddress((void**)&ATT, g_ATT);

    dim3 gemm_grid(LD / 128, CD / 128, NB);   // (50, 2, 8)
    hmma_gemm_kernel<<<gemm_grid, 256>>>(qf, Wq, bq, nullptr, Q);
    hmma_gemm_kernel<<<gemm_grid, 256>>>(kf, Wk, bk, nullptr, K);
    hmma_gemm_kernel<<<gemm_grid, 256>>>(vf, Wv, bv, nullptr, V);

    softmax_L_kernel<<<NB * CD, 256>>>(K);
    softmax_C_kernel<<<dim3(LD / 128, NHEADS, NB), 128>>>(Q);

    zero_ctx_kernel<<<(NB * NHEADS * HC * HC) / 256, 256>>>();
    context_kernel<<<dim3(10, NHEADS, NB), 256>>>();
    attend_kernel<<<dim3(LD / 128, NHEADS, NB), 128>>>();

    hmma_gemm_kernel<<<gemm_grid, 256>>>(ATT, Wr, br, qf, out);
}

// round 4
// speedup vs baseline: 1.9787x; 1.1238x over previous
#include <cuda_runtime.h>
#include <cuda_bf16.h>
#include <cstdint>

#define NB 8
#define CD 256
#define LD 6400
#define NHEADS 8
#define HC 32

// Scratch (device globals -- no allocation allowed)
__device__ float g_Q[NB * CD * LD];
__device__ float g_K[NB * CD * LD];
__device__ float g_V[NB * CD * LD];
__device__ float g_ATT[NB * CD * LD];
__device__ float g_CTX[NB * NHEADS * HC * HC];
__device__ float g_kmax[NB * CD];
__device__ float g_kinv[NB * CD];

// ---------------------------------------------------------------------------
// mma.sync / ldmatrix helpers (baseline PTX, works on compute_103)
// ---------------------------------------------------------------------------
__device__ __forceinline__ uint32_t smem_u32(const void* p) {
    uint32_t a;
    asm("{ .reg .u64 t; cvta.to.shared.u64 t, %1; cvt.u32.u64 %0, t; }"
        : "=r"(a) : "l"(p));
    return a;
}

__device__ __forceinline__ void ldsm4(uint32_t* r, uint32_t addr) {
    asm volatile("ldmatrix.sync.aligned.m8n8.x4.shared.b16 {%0,%1,%2,%3}, [%4];"
                 : "=r"(r[0]), "=r"(r[1]), "=r"(r[2]), "=r"(r[3]) : "r"(addr));
}
__device__ __forceinline__ void ldsm2t(uint32_t* r, uint32_t addr) {
    asm volatile("ldmatrix.sync.aligned.m8n8.x2.trans.shared.b16 {%0,%1}, [%2];"
                 : "=r"(r[0]), "=r"(r[1]) : "r"(addr));
}

__device__ __forceinline__ void mma16816(float* c, const uint32_t* a, const uint32_t* b) {
    asm volatile(
        "mma.sync.aligned.m16n8k16.row.col.f32.bf16.bf16.f32 "
        "{%0,%1,%2,%3}, {%4,%5,%6,%7}, {%8,%9}, {%0,%1,%2,%3};"
        : "+f"(c[0]), "+f"(c[1]), "+f"(c[2]), "+f"(c[3])
        : "r"(a[0]), "r"(a[1]), "r"(a[2]), "r"(a[3]), "r"(b[0]), "r"(b[1]));
}

// ---------------------------------------------------------------------------
// HMMA GEMM: Y[n, m, l] = sum_k W[m,k] * X[n,k,l] + bias[m] (+ resid)
// Block tile 128(m) x 128(l), BK=32, 8 warps (warp tile 32x64).
// bf16x2 split: acc += Ahi*Bhi + Ahi*Blo   (A = W rounded to bf16)
// Double-buffered smem, one sync per chunk.
// ---------------------------------------------------------------------------
#define SA 40    // bf16 stride of A smem rows (80B -> conflict-free ldmatrix)
#define SB 136   // bf16 stride of B smem rows (272B -> conflict-free ldmatrix)
#define ELA (128 * SA)           // 5120 bf16
#define ELBH (32 * SB)           // 4352 bf16
#define BUFEL (ELA + 2 * ELBH)   // per-buffer elements (13824)
#define GEMM_SMEM (2 * BUFEL * 2)  // bytes (55296)

__global__ __launch_bounds__(256) void hmma_gemm_kernel(
    const float* __restrict__ X, const float* __restrict__ W,
    const float* __restrict__ bias, const float* __restrict__ resid,
    float* __restrict__ Y)
{
    extern __shared__ __align__(16) __nv_bfloat16 dsm[];

    const int tid  = threadIdx.x;
    const int wid  = tid >> 5;
    const int lane = tid & 31;
    const int l0   = blockIdx.x * 128;
    const int m0   = blockIdx.y * 128;
    const int nb   = blockIdx.z;

    const int m0w = (wid & 3) * 32;   // warp m offset in block
    const int n0w = (wid >> 2) * 64;  // warp n offset in block

    const float* Xn = X + (size_t)nb * CD * LD;
    float* Yn = Y + (size_t)nb * CD * LD;
    const float* Rn = resid ? resid + (size_t)nb * CD * LD : nullptr;

    float acc[2][8][4];
#pragma unroll
    for (int i = 0; i < 2; i++)
#pragma unroll
        for (int j = 0; j < 8; j++)
#pragma unroll
            for (int e = 0; e < 4; e++) acc[i][j][e] = 0.0f;

    // ldmatrix lane address bases, per buffer
    const int a_tile = lane >> 3;
    const int a_row  = m0w + ((a_tile & 1) << 3) + (lane & 7);
    const int a_koff = (a_tile >> 1) << 3;
    const int b_k = lane & 15;

    uint32_t aHi[2], bHi[2], bLo[2];
    // smem store bases, per buffer
    __nv_bfloat16* Abuf[2];
    __nv_bfloat16* BHbuf[2];
    __nv_bfloat16* BLbuf[2];
#pragma unroll
    for (int b = 0; b < 2; ++b) {
        __nv_bfloat16* A  = dsm + b * BUFEL;
        __nv_bfloat16* BH = A + ELA;
        __nv_bfloat16* BL = BH + ELBH;
        Abuf[b] = A; BHbuf[b] = BH; BLbuf[b] = BL;
        aHi[b] = smem_u32(&A[a_row * SA + a_koff]);
        bHi[b] = smem_u32(&BH[b_k * SB + n0w]);
        bLo[b] = smem_u32(&BL[b_k * SB + n0w]);
    }

    const float4* W4 = (const float4*)W;
    const float4* X4 = (const float4*)Xn;

    float4 av[4], bv[4];

#define GEMM_LOADS(c)                                                          \
    {                                                                          \
        _Pragma("unroll")                                                      \
        for (int i = 0; i < 4; ++i) {                                          \
            int f4  = tid + i * 256;                                           \
            int row = f4 >> 3;                                                 \
            int kq  = f4 & 7;                                                  \
            av[i] = W4[(size_t)(m0 + row) * 64 + (c) * 8 + kq];                \
        }                                                                      \
        _Pragma("unroll")                                                      \
        for (int i = 0; i < 4; ++i) {                                          \
            int f4 = tid + i * 256;                                            \
            int k  = f4 >> 5;                                                  \
            int lq = f4 & 31;                                                  \
            bv[i] = X4[(size_t)((c) * 32 + k) * (LD / 4) + (l0 >> 2) + lq];    \
        }                                                                      \
    }

#define GEMM_STORES(b)                                                         \
    {                                                                          \
        _Pragma("unroll")                                                      \
        for (int i = 0; i < 4; ++i) {                                          \
            int f4  = tid + i * 256;                                           \
            int row = f4 >> 3;                                                 \
            int kq  = f4 & 7;                                                  \
            union { __nv_bfloat16 h[4]; unsigned long long u; } ua;            \
            ua.h[0] = __float2bfloat16(av[i].x);                               \
            ua.h[1] = __float2bfloat16(av[i].y);                               \
            ua.h[2] = __float2bfloat16(av[i].z);                               \
            ua.h[3] = __float2bfloat16(av[i].w);                               \
            *(unsigned long long*)&Abuf[b][row * SA + kq * 4] = ua.u;          \
        }                                                                      \
        _Pragma("unroll")                                                      \
        for (int i = 0; i < 4; ++i) {                                          \
            int f4 = tid + i * 256;                                            \
            int k  = f4 >> 5;                                                  \
            int lq = f4 & 31;                                                  \
            union { __nv_bfloat16 h[4]; unsigned long long u; } uh, ul;        \
            float vv[4] = {bv[i].x, bv[i].y, bv[i].z, bv[i].w};                \
            _Pragma("unroll")                                                  \
            for (int e = 0; e < 4; ++e) {                                      \
                __nv_bfloat16 h = __float2bfloat16(vv[e]);                     \
                uh.h[e] = h;                                                   \
                ul.h[e] = __float2bfloat16(vv[e] - __bfloat162float(h));       \
            }                                                                  \
            *(unsigned long long*)&BHbuf[b][k * SB + lq * 4] = uh.u;           \
            *(unsigned long long*)&BLbuf[b][k * SB + lq * 4] = ul.u;           \
        }                                                                      \
    }

    // prologue: chunk 0
    GEMM_LOADS(0);
    GEMM_STORES(0);
    __syncthreads();

    for (int c = 0; c < 8; ++c) {
        if (c < 7) GEMM_LOADS(c + 1);

        const int b = c & 1;
#pragma unroll
        for (int ks = 0; ks < 2; ++ks) {
            uint32_t a_hi[2][4];
#pragma unroll
            for (int im = 0; im < 2; ++im) {
                uint32_t ofs = (uint32_t)(im * 16 * SA + ks * 16) * 2;
                ldsm4(a_hi[im], aHi[b] + ofs);
            }
#pragma unroll
            for (int jn = 0; jn < 8; ++jn) {
                uint32_t b_hi[2], b_lo[2];
                uint32_t ofs = (uint32_t)(ks * 16 * SB + jn * 8) * 2;
                ldsm2t(b_hi, bHi[b] + ofs);
                ldsm2t(b_lo, bLo[b] + ofs);
#pragma unroll
                for (int im = 0; im < 2; ++im) {
                    mma16816(acc[im][jn], a_hi[im], b_hi);
                    mma16816(acc[im][jn], a_hi[im], b_lo);
                }
            }
        }

        if (c < 7) GEMM_STORES((c + 1) & 1);
        __syncthreads();
    }

    // ---- epilogue: regs -> global, + bias (+ residual)
    const int qr = lane >> 2;        // 0..7
    const int qc = (lane & 3) * 2;   // 0,2,4,6
#pragma unroll
    for (int im = 0; im < 2; ++im) {
        int mA = m0 + m0w + im * 16 + qr;
        int mB = mA + 8;
        float bA = bias[mA];
        float bB = bias[mB];
#pragma unroll
        for (int jn = 0; jn < 8; ++jn) {
            int n = l0 + n0w + jn * 8 + qc;
            size_t gA = (size_t)mA * LD + n;
            size_t gB = (size_t)mB * LD + n;
            float o0 = acc[im][jn][0] + bA;
            float o1 = acc[im][jn][1] + bA;
            float o2 = acc[im][jn][2] + bB;
            float o3 = acc[im][jn][3] + bB;
            if (Rn) {
                float2 rA = *(const float2*)(Rn + gA);
                float2 rB = *(const float2*)(Rn + gB);
                o0 += rA.x; o1 += rA.y; o2 += rB.x; o3 += rB.y;
            }
            float2 vA = {o0, o1};
            float2 vB = {o2, o3};
            *(float2*)(Yn + gA) = vA;
            *(float2*)(Yn + gB) = vB;
        }
    }
}

// ---------------------------------------------------------------------------
// K row stats: max and 1/sum(exp(v - max)) per (n, channel) row of g_K.
// One block (256 thr) per row; 25 elements per thread held in registers.
// ---------------------------------------------------------------------------
__global__ __launch_bounds__(256) void kstats_kernel()
{
    __shared__ float red[256];
    const int row = blockIdx.x;
    const float* r = g_K + (size_t)row * LD;
    const int tid = threadIdx.x;

    float v[25];
    float mx = -1e30f;
#pragma unroll
    for (int i = 0; i < 25; ++i) {
        v[i] = r[tid + i * 256];
        mx = fmaxf(mx, v[i]);
    }
    red[tid] = mx;
    __syncthreads();
    for (int s = 128; s > 0; s >>= 1) {
        if (tid < s) red[tid] = fmaxf(red[tid], red[tid + s]);
        __syncthreads();
    }
    mx = red[0];
    __syncthreads();

    float sm = 0.0f;
#pragma unroll
    for (int i = 0; i < 25; ++i) sm += __expf(v[i] - mx);
    red[tid] = sm;
    __syncthreads();
    for (int s = 128; s > 0; s >>= 1) {
        if (tid < s) red[tid] += red[tid + s];
        __syncthreads();
    }
    if (tid == 0) {
        g_kmax[row] = mx;
        g_kinv[row] = 1.0f / red[0];
    }
}

__global__ void zero_ctx_kernel()
{
    g_CTX[blockIdx.x * 256 + threadIdx.x] = 0.0f;
}

// ---------------------------------------------------------------------------
// context[n,h,kc,vc] = sum_l softmax_L(K)[n,h,kc,l] * V[n,h,vc,l]
// K softmax applied inline via g_kmax/g_kinv.
// ---------------------------------------------------------------------------
__global__ __launch_bounds__(256) void context_kernel()
{
    __shared__ float sk[32][129];
    __shared__ float sv[32][129];
    const int n = blockIdx.z, h = blockIdx.y;
    const size_t base = (((size_t)n * NHEADS + h) * HC) * LD;
    const int rowbase = n * CD + h * HC;
    const int tid = threadIdx.x;
    const int kc = tid >> 3;
    const int vg = (tid & 7) * 4;

    float acc0 = 0.f, acc1 = 0.f, acc2 = 0.f, acc3 = 0.f;

    for (int t = 0; t < 5; ++t) {
        const int l0 = blockIdx.x * 640 + t * 128;
#pragma unroll
        for (int s = 0; s < 16; s++) {
            int idx = tid + s * 256;
            int c = idx >> 7, l = idx & 127;
            float kraw = g_K[base + (size_t)c * LD + l0 + l];
            sk[c][l] = __expf(kraw - g_kmax[rowbase + c]);
            sv[c][l] = g_V[base + (size_t)c * LD + l0 + l];
        }
        __syncthreads();
#pragma unroll 4
        for (int l = 0; l < 128; l++) {
            float a = sk[kc][l];
            acc0 += a * sv[vg + 0][l];
            acc1 += a * sv[vg + 1][l];
            acc2 += a * sv[vg + 2][l];
            acc3 += a * sv[vg + 3][l];
        }
        __syncthreads();
    }
    float inv = g_kinv[rowbase + kc];
    const size_t cb = (((size_t)n * NHEADS + h) * HC + kc) * HC + vg;
    atomicAdd(&g_CTX[cb + 0], acc0 * inv);
    atomicAdd(&g_CTX[cb + 1], acc1 * inv);
    atomicAdd(&g_CTX[cb + 2], acc2 * inv);
    atomicAdd(&g_CTX[cb + 3], acc3 * inv);
}

// ---------------------------------------------------------------------------
// attended[n,h,vc,l] = sum_kc ctx[n,h,kc,vc] * softmax_C(q)[n,h,kc,l]
// Q softmax over the 32 in-head channels fused (register-resident).
// ---------------------------------------------------------------------------
__global__ __launch_bounds__(128) void attend_kernel()
{
    __shared__ float4 sctx[32][8];
    const int n = blockIdx.z, h = blockIdx.y;
    const int tid = threadIdx.x;
    {
        const float4* C = (const float4*)(g_CTX + (((size_t)n * NHEADS + h) * HC) * HC);
#pragma unroll
        for (int s = 0; s < 2; s++) {
            int idx = tid + s * 128;
            sctx[idx >> 3][idx & 7] = C[idx];
        }
    }
    __syncthreads();

    const int l = blockIdx.x * 128 + tid;
    const size_t base = (((size_t)n * NHEADS + h) * HC) * LD + l;

    float q[HC];
    float mx = -1e30f;
#pragma unroll
    for (int c = 0; c < HC; c++) {
        q[c] = g_Q[base + (size_t)c * LD];
        mx = fmaxf(mx, q[c]);
    }
    float s = 0.0f;
#pragma unroll
    for (int c = 0; c < HC; c++) {
        q[c] = __expf(q[c] - mx);
        s += q[c];
    }
    float inv = 1.0f / s;
#pragma unroll
    for (int c = 0; c < HC; c++) q[c] *= inv;

    float acc[HC];
#pragma unroll
    for (int v = 0; v < HC; v++) acc[v] = 0.0f;

#pragma unroll
    for (int kc = 0; kc < HC; kc++) {
        float a = q[kc];
#pragma unroll
        for (int vq = 0; vq < 8; vq++) {
            float4 c4 = sctx[kc][vq];
            acc[vq * 4 + 0] += a * c4.x;
            acc[vq * 4 + 1] += a * c4.y;
            acc[vq * 4 + 2] += a * c4.z;
            acc[vq * 4 + 3] += a * c4.w;
        }
    }
#pragma unroll
    for (int v = 0; v < HC; v++) g_ATT[base + (size_t)v * LD] = acc[v];
}

// ---------------------------------------------------------------------------
extern "C" void kernel_launch(void* const* d_in, const int* in_sizes, int n_in,
                              void* d_out, int out_size)
{
    const float* qf = (const float*)d_in[0];
    const float* kf = (const float*)d_in[1];
    const float* vf = (const float*)d_in[2];
    const float* Wq = (const float*)d_in[3];
    const float* bq = (const float*)d_in[4];
    const float* Wk = (const float*)d_in[5];
    const float* bk = (const float*)d_in[6];
    const float* Wv = (const float*)d_in[7];
    const float* bv = (const float*)d_in[8];
    const float* Wr = (const float*)d_in[9];
    const float* br = (const float*)d_in[10];
    float* out = (float*)d_out;

    float *Q, *K, *V, *ATT;
    cudaGetSymbolAddress((void**)&Q,   g_Q);
    cudaGetSymbolAddress((void**)&K,   g_K);
    cudaGetSymbolAddress((void**)&V,   g_V);
    cudaGetSymbolAddress((void**)&ATT, g_ATT);

    cudaFuncSetAttribute(hmma_gemm_kernel,
                         cudaFuncAttributeMaxDynamicSharedMemorySize, GEMM_SMEM);

    dim3 gemm_grid(LD / 128, CD / 128, NB);   // (50, 2, 8)
    hmma_gemm_kernel<<<gemm_grid, 256, GEMM_SMEM>>>(qf, Wq, bq, nullptr, Q);
    hmma_gemm_kernel<<<gemm_grid, 256, GEMM_SMEM>>>(kf, Wk, bk, nullptr, K);
    hmma_gemm_kernel<<<gemm_grid, 256, GEMM_SMEM>>>(vf, Wv, bv, nullptr, V);

    kstats_kernel<<<NB * CD, 256>>>();
    zero_ctx_kernel<<<(NB * NHEADS * HC * HC) / 256, 256>>>();
    context_kernel<<<dim3(10, NHEADS, NB), 256>>>();
    attend_kernel<<<dim3(LD / 128, NHEADS, NB), 128>>>();

    hmma_gemm_kernel<<<gemm_grid, 256, GEMM_SMEM>>>(ATT, Wr, br, qf, out);
}

// round 5
// speedup vs baseline: 2.3386x; 1.1819x over previous
#include <cuda_runtime.h>
#include <cuda_bf16.h>
#include <cstdint>

#define NB 8
#define CD 256
#define LD 6400
#define NHEADS 8
#define HC 32

// Scratch (device globals -- no allocation allowed)
__device__ float g_Q[NB * CD * LD];
__device__ float g_K[NB * CD * LD];
__device__ float g_V[NB * CD * LD];
__device__ float g_ATT[NB * CD * LD];
__device__ float g_CTX[NB * NHEADS * HC * HC];
__device__ float g_kmax[NB * CD];
__device__ float g_kinv[NB * CD];

// ---------------------------------------------------------------------------
// mma.sync / ldmatrix helpers (baseline PTX, works on compute_103)
// ---------------------------------------------------------------------------
__device__ __forceinline__ uint32_t smem_u32(const void* p) {
    uint32_t a;
    asm("{ .reg .u64 t; cvta.to.shared.u64 t, %1; cvt.u32.u64 %0, t; }"
        : "=r"(a) : "l"(p));
    return a;
}

__device__ __forceinline__ void ldsm4(uint32_t* r, uint32_t addr) {
    asm volatile("ldmatrix.sync.aligned.m8n8.x4.shared.b16 {%0,%1,%2,%3}, [%4];"
                 : "=r"(r[0]), "=r"(r[1]), "=r"(r[2]), "=r"(r[3]) : "r"(addr));
}
__device__ __forceinline__ void ldsm4t(uint32_t* r, uint32_t addr) {
    asm volatile("ldmatrix.sync.aligned.m8n8.x4.trans.shared.b16 {%0,%1,%2,%3}, [%4];"
                 : "=r"(r[0]), "=r"(r[1]), "=r"(r[2]), "=r"(r[3]) : "r"(addr));
}

__device__ __forceinline__ void mma16816(float* c, const uint32_t* a,
                                         uint32_t b0, uint32_t b1) {
    asm volatile(
        "mma.sync.aligned.m16n8k16.row.col.f32.bf16.bf16.f32 "
        "{%0,%1,%2,%3}, {%4,%5,%6,%7}, {%8,%9}, {%0,%1,%2,%3};"
        : "+f"(c[0]), "+f"(c[1]), "+f"(c[2]), "+f"(c[3])
        : "r"(a[0]), "r"(a[1]), "r"(a[2]), "r"(a[3]), "r"(b0), "r"(b1));
}

// ---------------------------------------------------------------------------
// HMMA GEMM: Y[n, m, l] = sum_k W[m,k] * X[n,k,l] + bias[m] (+ resid)
// Block tile 128(m) x 128(l), BK=32, 8 warps (warp tile 32x64).
// Pure bf16 operands (single product), fp32 accumulate.
// Double-buffered smem, one sync per chunk.
// ---------------------------------------------------------------------------
#define SA 40    // bf16 stride of A smem rows (80B -> conflict-free ldmatrix)
#define SB 136   // bf16 stride of B smem rows (272B -> conflict-free ldmatrix)
#define ELA (128 * SA)           // 5120 bf16
#define ELB (32 * SB)            // 4352 bf16
#define BUFEL (ELA + ELB)        // per-buffer elements (9472)
#define GEMM_SMEM (2 * BUFEL * 2)  // bytes (37888)

__global__ __launch_bounds__(256, 2) void hmma_gemm_kernel(
    const float* __restrict__ X, const float* __restrict__ W,
    const float* __restrict__ bias, const float* __restrict__ resid,
    float* __restrict__ Y)
{
    extern __shared__ __align__(16) __nv_bfloat16 dsm[];

    const int tid  = threadIdx.x;
    const int wid  = tid >> 5;
    const int lane = tid & 31;
    const int l0   = blockIdx.x * 128;
    const int m0   = blockIdx.y * 128;
    const int nb   = blockIdx.z;

    const int m0w = (wid & 3) * 32;   // warp m offset in block
    const int n0w = (wid >> 2) * 64;  // warp n offset in block

    const float* Xn = X + (size_t)nb * CD * LD;
    float* Yn = Y + (size_t)nb * CD * LD;
    const float* Rn = resid ? resid + (size_t)nb * CD * LD : nullptr;

    float acc[2][8][4];
#pragma unroll
    for (int i = 0; i < 2; i++)
#pragma unroll
        for (int j = 0; j < 8; j++)
#pragma unroll
            for (int e = 0; e < 4; e++) acc[i][j][e] = 0.0f;

    // ldmatrix lane address bases, per buffer
    const int a_tile = lane >> 3;
    const int a_row  = m0w + ((a_tile & 1) << 3) + (lane & 7);
    const int a_koff = (a_tile >> 1) << 3;
    // B x4.trans: lanes 0-15 -> k rows at col n0; lanes 16-31 -> k rows at n0+8
    const int b_k = lane & 15;
    const int b_n = n0w + ((lane >> 4) << 3);

    uint32_t aHi[2], bHi[2];
    __nv_bfloat16* Abuf[2];
    __nv_bfloat16* Bbuf[2];
#pragma unroll
    for (int b = 0; b < 2; ++b) {
        __nv_bfloat16* A  = dsm + b * BUFEL;
        __nv_bfloat16* BH = A + ELA;
        Abuf[b] = A; Bbuf[b] = BH;
        aHi[b] = smem_u32(&A[a_row * SA + a_koff]);
        bHi[b] = smem_u32(&BH[b_k * SB + b_n]);
    }

    const float4* W4 = (const float4*)W;
    const float4* X4 = (const float4*)Xn;

    float4 av[4], bv[4];

#define GEMM_LOADS(c)                                                          \
    {                                                                          \
        _Pragma("unroll")                                                      \
        for (int i = 0; i < 4; ++i) {                                          \
            int f4  = tid + i * 256;                                           \
            int row = f4 >> 3;                                                 \
            int kq  = f4 & 7;                                                  \
            av[i] = W4[(size_t)(m0 + row) * 64 + (c) * 8 + kq];                \
        }                                                                      \
        _Pragma("unroll")                                                      \
        for (int i = 0; i < 4; ++i) {                                          \
            int f4 = tid + i * 256;                                            \
            int k  = f4 >> 5;                                                  \
            int lq = f4 & 31;                                                  \
            bv[i] = X4[(size_t)((c) * 32 + k) * (LD / 4) + (l0 >> 2) + lq];    \
        }                                                                      \
    }

#define GEMM_STORES(b)                                                         \
    {                                                                          \
        _Pragma("unroll")                                                      \
        for (int i = 0; i < 4; ++i) {                                          \
            int f4  = tid + i * 256;                                           \
            int row = f4 >> 3;                                                 \
            int kq  = f4 & 7;                                                  \
            union { __nv_bfloat162 h[2]; unsigned long long u; } ua;           \
            ua.h[0] = __float22bfloat162_rn(make_float2(av[i].x, av[i].y));    \
            ua.h[1] = __float22bfloat162_rn(make_float2(av[i].z, av[i].w));    \
            *(unsigned long long*)&Abuf[b][row * SA + kq * 4] = ua.u;          \
        }                                                                      \
        _Pragma("unroll")                                                      \
        for (int i = 0; i < 4; ++i) {                                          \
            int f4 = tid + i * 256;                                            \
            int k  = f4 >> 5;                                                  \
            int lq = f4 & 31;                                                  \
            union { __nv_bfloat162 h[2]; unsigned long long u; } ub;           \
            ub.h[0] = __float22bfloat162_rn(make_float2(bv[i].x, bv[i].y));    \
            ub.h[1] = __float22bfloat162_rn(make_float2(bv[i].z, bv[i].w));    \
            *(unsigned long long*)&Bbuf[b][k * SB + lq * 4] = ub.u;            \
        }                                                                      \
    }

    // prologue: chunk 0
    GEMM_LOADS(0);
    GEMM_STORES(0);
    __syncthreads();

    for (int c = 0; c < 8; ++c) {
        if (c < 7) GEMM_LOADS(c + 1);

        const int b = c & 1;
#pragma unroll
        for (int ks = 0; ks < 2; ++ks) {
            uint32_t a_hi[2][4];
#pragma unroll
            for (int im = 0; im < 2; ++im) {
                uint32_t ofs = (uint32_t)(im * 16 * SA + ks * 16) * 2;
                ldsm4(a_hi[im], aHi[b] + ofs);
            }
#pragma unroll
            for (int jp = 0; jp < 4; ++jp) {
                uint32_t b4[4];
                uint32_t ofs = (uint32_t)(ks * 16 * SB + jp * 16) * 2;
                ldsm4t(b4, bHi[b] + ofs);
#pragma unroll
                for (int im = 0; im < 2; ++im) {
                    mma16816(acc[im][jp * 2 + 0], a_hi[im], b4[0], b4[1]);
                    mma16816(acc[im][jp * 2 + 1], a_hi[im], b4[2], b4[3]);
                }
            }
        }

        if (c < 7) GEMM_STORES((c + 1) & 1);
        __syncthreads();
    }

    // ---- epilogue: regs -> global, + bias (+ residual)
    const int qr = lane >> 2;        // 0..7
    const int qc = (lane & 3) * 2;   // 0,2,4,6
#pragma unroll
    for (int im = 0; im < 2; ++im) {
        int mA = m0 + m0w + im * 16 + qr;
        int mB = mA + 8;
        float bA = bias[mA];
        float bB = bias[mB];
#pragma unroll
        for (int jn = 0; jn < 8; ++jn) {
            int n = l0 + n0w + jn * 8 + qc;
            size_t gA = (size_t)mA * LD + n;
            size_t gB = (size_t)mB * LD + n;
            float o0 = acc[im][jn][0] + bA;
            float o1 = acc[im][jn][1] + bA;
            float o2 = acc[im][jn][2] + bB;
            float o3 = acc[im][jn][3] + bB;
            if (Rn) {
                float2 rA = *(const float2*)(Rn + gA);
                float2 rB = *(const float2*)(Rn + gB);
                o0 += rA.x; o1 += rA.y; o2 += rB.x; o3 += rB.y;
            }
            float2 vA = {o0, o1};
            float2 vB = {o2, o3};
            *(float2*)(Yn + gA) = vA;
            *(float2*)(Yn + gB) = vB;
        }
    }
}

// ---------------------------------------------------------------------------
// K row stats: max and 1/sum(exp(v - max)) per (n, channel) row of g_K.
// ---------------------------------------------------------------------------
__global__ __launch_bounds__(256) void kstats_kernel()
{
    __shared__ float red[256];
    const int row = blockIdx.x;
    const float* r = g_K + (size_t)row * LD;
    const int tid = threadIdx.x;

    float v[25];
    float mx = -1e30f;
#pragma unroll
    for (int i = 0; i < 25; ++i) {
        v[i] = r[tid + i * 256];
        mx = fmaxf(mx, v[i]);
    }
    red[tid] = mx;
    __syncthreads();
    for (int s = 128; s > 0; s >>= 1) {
        if (tid < s) red[tid] = fmaxf(red[tid], red[tid + s]);
        __syncthreads();
    }
    mx = red[0];
    __syncthreads();

    float sm = 0.0f;
#pragma unroll
    for (int i = 0; i < 25; ++i) sm += __expf(v[i] - mx);
    red[tid] = sm;
    __syncthreads();
    for (int s = 128; s > 0; s >>= 1) {
        if (tid < s) red[tid] += red[tid + s];
        __syncthreads();
    }
    if (tid == 0) {
        g_kmax[row] = mx;
        g_kinv[row] = 1.0f / red[0];
    }
}

__global__ void zero_ctx_kernel()
{
    g_CTX[blockIdx.x * 256 + threadIdx.x] = 0.0f;
}

// ---------------------------------------------------------------------------
// context[n,h,kc,vc] = sum_l softmax_L(K)[n,h,kc,l] * V[n,h,vc,l]
// ---------------------------------------------------------------------------
__global__ __launch_bounds__(256) void context_kernel()
{
    __shared__ float sk[32][129];
    __shared__ float sv[32][129];
    const int n = blockIdx.z, h = blockIdx.y;
    const size_t base = (((size_t)n * NHEADS + h) * HC) * LD;
    const int rowbase = n * CD + h * HC;
    const int tid = threadIdx.x;
    const int kc = tid >> 3;
    const int vg = (tid & 7) * 4;

    float acc0 = 0.f, acc1 = 0.f, acc2 = 0.f, acc3 = 0.f;

    for (int t = 0; t < 5; ++t) {
        const int l0 = blockIdx.x * 640 + t * 128;
#pragma unroll
        for (int s = 0; s < 16; s++) {
            int idx = tid + s * 256;
            int c = idx >> 7, l = idx & 127;
            float kraw = g_K[base + (size_t)c * LD + l0 + l];
            sk[c][l] = __expf(kraw - g_kmax[rowbase + c]);
            sv[c][l] = g_V[base + (size_t)c * LD + l0 + l];
        }
        __syncthreads();
#pragma unroll 4
        for (int l = 0; l < 128; l++) {
            float a = sk[kc][l];
            acc0 += a * sv[vg + 0][l];
            acc1 += a * sv[vg + 1][l];
            acc2 += a * sv[vg + 2][l];
            acc3 += a * sv[vg + 3][l];
        }
        __syncthreads();
    }
    float inv = g_kinv[rowbase + kc];
    const size_t cb = (((size_t)n * NHEADS + h) * HC + kc) * HC + vg;
    atomicAdd(&g_CTX[cb + 0], acc0 * inv);
    atomicAdd(&g_CTX[cb + 1], acc1 * inv);
    atomicAdd(&g_CTX[cb + 2], acc2 * inv);
    atomicAdd(&g_CTX[cb + 3], acc3 * inv);
}

// ---------------------------------------------------------------------------
// attended[n,h,vc,l] = sum_kc ctx[n,h,kc,vc] * softmax_C(q)[n,h,kc,l]
// ---------------------------------------------------------------------------
__global__ __launch_bounds__(128) void attend_kernel()
{
    __shared__ float4 sctx[32][8];
    const int n = blockIdx.z, h = blockIdx.y;
    const int tid = threadIdx.x;
    {
        const float4* C = (const float4*)(g_CTX + (((size_t)n * NHEADS + h) * HC) * HC);
#pragma unroll
        for (int s = 0; s < 2; s++) {
            int idx = tid + s * 128;
            sctx[idx >> 3][idx & 7] = C[idx];
        }
    }
    __syncthreads();

    const int l = blockIdx.x * 128 + tid;
    const size_t base = (((size_t)n * NHEADS + h) * HC) * LD + l;

    float q[HC];
    float mx = -1e30f;
#pragma unroll
    for (int c = 0; c < HC; c++) {
        q[c] = g_Q[base + (size_t)c * LD];
        mx = fmaxf(mx, q[c]);
    }
    float s = 0.0f;
#pragma unroll
    for (int c = 0; c < HC; c++) {
        q[c] = __expf(q[c] - mx);
        s += q[c];
    }
    float inv = 1.0f / s;
#pragma unroll
    for (int c = 0; c < HC; c++) q[c] *= inv;

    float acc[HC];
#pragma unroll
    for (int v = 0; v < HC; v++) acc[v] = 0.0f;

#pragma unroll
    for (int kc = 0; kc < HC; kc++) {
        float a = q[kc];
#pragma unroll
        for (int vq = 0; vq < 8; vq++) {
            float4 c4 = sctx[kc][vq];
            acc[vq * 4 + 0] += a * c4.x;
            acc[vq * 4 + 1] += a * c4.y;
            acc[vq * 4 + 2] += a * c4.z;
            acc[vq * 4 + 3] += a * c4.w;
        }
    }
#pragma unroll
    for (int v = 0; v < HC; v++) g_ATT[base + (size_t)v * LD] = acc[v];
}

// ---------------------------------------------------------------------------
extern "C" void kernel_launch(void* const* d_in, const int* in_sizes, int n_in,
                              void* d_out, int out_size)
{
    const float* qf = (const float*)d_in[0];
    const float* kf = (const float*)d_in[1];
    const float* vf = (const float*)d_in[2];
    const float* Wq = (const float*)d_in[3];
    const float* bq = (const float*)d_in[4];
    const float* Wk = (const float*)d_in[5];
    const float* bk = (const float*)d_in[6];
    const float* Wv = (const float*)d_in[7];
    const float* bv = (const float*)d_in[8];
    const float* Wr = (const float*)d_in[9];
    const float* br = (const float*)d_in[10];
    float* out = (float*)d_out;

    float *Q, *K, *V, *ATT;
    cudaGetSymbolAddress((void**)&Q,   g_Q);
    cudaGetSymbolAddress((void**)&K,   g_K);
    cudaGetSymbolAddress((void**)&V,   g_V);
    cudaGetSymbolAddress((void**)&ATT, g_ATT);

    cudaFuncSetAttribute(hmma_gemm_kernel,
                         cudaFuncAttributeMaxDynamicSharedMemorySize, GEMM_SMEM);

    dim3 gemm_grid(LD / 128, CD / 128, NB);   // (50, 2, 8)
    hmma_gemm_kernel<<<gemm_grid, 256, GEMM_SMEM>>>(kf, Wk, bk, nullptr, K);
    hmma_gemm_kernel<<<gemm_grid, 256, GEMM_SMEM>>>(qf, Wq, bq, nullptr, Q);
    hmma_gemm_kernel<<<gemm_grid, 256, GEMM_SMEM>>>(vf, Wv, bv, nullptr, V);

    kstats_kernel<<<NB * CD, 256>>>();
    zero_ctx_kernel<<<(NB * NHEADS * HC * HC) / 256, 256>>>();
    context_kernel<<<dim3(10, NHEADS, NB), 256>>>();
    attend_kernel<<<dim3(LD / 128, NHEADS, NB), 128>>>();

    hmma_gemm_kernel<<<gemm_grid, 256, GEMM_SMEM>>>(ATT, Wr, br, qf, out);
}

// round 6
// speedup vs baseline: 2.3605x; 1.0094x over previous
#include <cuda_runtime.h>
#include <cuda_bf16.h>
#include <cstdint>

#define NB 8
#define CD 256
#define LD 6400
#define NHEADS 8
#define HC 32

// Scratch (device globals -- no allocation allowed)
__device__ float g_Q[NB * CD * LD];
__device__ float g_K[NB * CD * LD];
__device__ float g_V[NB * CD * LD];
__device__ float g_ATT[NB * CD * LD];
__device__ float g_CTX[NB * NHEADS * HC * HC];
__device__ float g_kmax[NB * CD];
__device__ float g_kinv[NB * CD];

// ---------------------------------------------------------------------------
// mma.sync / ldmatrix / cp.async helpers (baseline PTX, works on compute_103)
// ---------------------------------------------------------------------------
__device__ __forceinline__ uint32_t smem_u32(const void* p) {
    uint32_t a;
    asm("{ .reg .u64 t; cvta.to.shared.u64 t, %1; cvt.u32.u64 %0, t; }"
        : "=r"(a) : "l"(p));
    return a;
}

__device__ __forceinline__ void ldsm4(uint32_t* r, uint32_t addr) {
    asm volatile("ldmatrix.sync.aligned.m8n8.x4.shared.b16 {%0,%1,%2,%3}, [%4];"
                 : "=r"(r[0]), "=r"(r[1]), "=r"(r[2]), "=r"(r[3]) : "r"(addr));
}
__device__ __forceinline__ void ldsm4t(uint32_t* r, uint32_t addr) {
    asm volatile("ldmatrix.sync.aligned.m8n8.x4.trans.shared.b16 {%0,%1,%2,%3}, [%4];"
                 : "=r"(r[0]), "=r"(r[1]), "=r"(r[2]), "=r"(r[3]) : "r"(addr));
}

__device__ __forceinline__ void mma16816(float* c, const uint32_t* a,
                                         uint32_t b0, uint32_t b1) {
    asm volatile(
        "mma.sync.aligned.m16n8k16.row.col.f32.bf16.bf16.f32 "
        "{%0,%1,%2,%3}, {%4,%5,%6,%7}, {%8,%9}, {%0,%1,%2,%3};"
        : "+f"(c[0]), "+f"(c[1]), "+f"(c[2]), "+f"(c[3])
        : "r"(a[0]), "r"(a[1]), "r"(a[2]), "r"(a[3]), "r"(b0), "r"(b1));
}

__device__ __forceinline__ void cpasync16(uint32_t saddr, const void* g) {
    asm volatile("cp.async.cg.shared.global [%0], [%1], 16;"
                 :: "r"(saddr), "l"(g) : "memory");
}
__device__ __forceinline__ void cpasync_commit() {
    asm volatile("cp.async.commit_group;" ::: "memory");
}
__device__ __forceinline__ void cpasync_wait0() {
    asm volatile("cp.async.wait_group 0;" ::: "memory");
}

// ---------------------------------------------------------------------------
// HMMA GEMM: Y[n, m, l] = sum_k W[m,k] * X[n,k,l] + bias[m] (+ resid)
// Block tile 128(m) x 128(l), BK=32, 8 warps (warp tile 32x64).
// Pure bf16 operands, fp32 accumulate.
// B staged via cp.async (fp32) -> convert to bf16 after compute; no B prefetch
// registers -> fits 128-reg cap at occupancy 2 without spills.
// ---------------------------------------------------------------------------
#define SA 40    // bf16 stride of A smem rows (80B -> conflict-free ldmatrix)
#define SB 136   // bf16 stride of B smem rows (272B -> conflict-free ldmatrix)
#define ELA (128 * SA)           // 5120 bf16
#define ELB (32 * SB)            // 4352 bf16
#define BUFEL (ELA + ELB)        // per-buffer elements (9472)
#define STAGEF 4096              // fp32 elements per stage (32k x 128l)
#define GEMM_SMEM (2 * BUFEL * 2 + 2 * STAGEF * 4)   // 37888 + 32768 = 70656

__global__ __launch_bounds__(256, 2) void hmma_gemm_kernel(
    const float* __restrict__ X, const float* __restrict__ W,
    const float* __restrict__ bias, const float* __restrict__ resid,
    float* __restrict__ Y)
{
    extern __shared__ __align__(16) __nv_bfloat16 dsm[];
    float* stage = (float*)(dsm + 2 * BUFEL);

    const int tid  = threadIdx.x;
    const int wid  = tid >> 5;
    const int lane = tid & 31;
    const int l0   = blockIdx.x * 128;
    const int m0   = blockIdx.y * 128;
    const int nb   = blockIdx.z;

    const int m0w = (wid & 3) * 32;   // warp m offset in block
    const int n0w = (wid >> 2) * 64;  // warp n offset in block

    const float* Xn = X + (size_t)nb * CD * LD;
    float* Yn = Y + (size_t)nb * CD * LD;
    const float* Rn = resid ? resid + (size_t)nb * CD * LD : nullptr;

    float acc[2][8][4];
#pragma unroll
    for (int i = 0; i < 2; i++)
#pragma unroll
        for (int j = 0; j < 8; j++)
#pragma unroll
            for (int e = 0; e < 4; e++) acc[i][j][e] = 0.0f;

    // ldmatrix lane address bases, per buffer
    const int a_tile = lane >> 3;
    const int a_row  = m0w + ((a_tile & 1) << 3) + (lane & 7);
    const int a_koff = (a_tile >> 1) << 3;
    const int b_k = lane & 15;
    const int b_n = n0w + ((lane >> 4) << 3);

    uint32_t aHi[2], bHi[2];
    __nv_bfloat16* Abuf[2];
    __nv_bfloat16* Bbuf[2];
#pragma unroll
    for (int b = 0; b < 2; ++b) {
        __nv_bfloat16* A  = dsm + b * BUFEL;
        __nv_bfloat16* BH = A + ELA;
        Abuf[b] = A; Bbuf[b] = BH;
        aHi[b] = smem_u32(&A[a_row * SA + a_koff]);
        bHi[b] = smem_u32(&BH[b_k * SB + b_n]);
    }
    // per-thread stage addresses (same mapping for write and read-back)
    const int st_k  = tid >> 5;        // 0..7 (+8 per i)
    const int st_lq = tid & 31;
    uint32_t stAddr[2];
    stAddr[0] = smem_u32(&stage[st_k * 128 + st_lq * 4]);
    stAddr[1] = smem_u32(&stage[STAGEF + st_k * 128 + st_lq * 4]);

    const float4* W4 = (const float4*)W;
    const float4* X4 = (const float4*)Xn;

    float4 av[4];

#define B_ASYNC(c, sb)                                                         \
    {                                                                          \
        _Pragma("unroll")                                                      \
        for (int i = 0; i < 4; ++i) {                                          \
            const float4* g =                                                  \
                X4 + (size_t)((c) * 32 + st_k + i * 8) * (LD / 4) +            \
                (l0 >> 2) + st_lq;                                             \
            cpasync16(stAddr[sb] + (uint32_t)(i * 8 * 128 * 4), g);            \
        }                                                                      \
        cpasync_commit();                                                      \
    }

#define A_LOADS(c)                                                             \
    {                                                                          \
        _Pragma("unroll")                                                      \
        for (int i = 0; i < 4; ++i) {                                          \
            int f4  = tid + i * 256;                                           \
            int row = f4 >> 3;                                                 \
            int kq  = f4 & 7;                                                  \
            av[i] = W4[(size_t)(m0 + row) * 64 + (c) * 8 + kq];                \
        }                                                                      \
    }

#define CONVERT(b, sb)                                                         \
    {                                                                          \
        _Pragma("unroll")                                                      \
        for (int i = 0; i < 4; ++i) {                                          \
            int f4  = tid + i * 256;                                           \
            int row = f4 >> 3;                                                 \
            int kq  = f4 & 7;                                                  \
            union { __nv_bfloat162 h[2]; unsigned long long u; } ua;           \
            ua.h[0] = __float22bfloat162_rn(make_float2(av[i].x, av[i].y));    \
            ua.h[1] = __float22bfloat162_rn(make_float2(av[i].z, av[i].w));    \
            *(unsigned long long*)&Abuf[b][row * SA + kq * 4] = ua.u;          \
        }                                                                      \
        _Pragma("unroll")                                                      \
        for (int i = 0; i < 4; ++i) {                                          \
            int k  = st_k + i * 8;                                             \
            float4 v = *(const float4*)&stage[(sb) * STAGEF + k * 128 +        \
                                              st_lq * 4];                      \
            union { __nv_bfloat162 h[2]; unsigned long long u; } ub;           \
            ub.h[0] = __float22bfloat162_rn(make_float2(v.x, v.y));            \
            ub.h[1] = __float22bfloat162_rn(make_float2(v.z, v.w));            \
            *(unsigned long long*)&Bbuf[b][k * SB + st_lq * 4] = ub.u;         \
        }                                                                      \
    }

    // prologue: chunk 0
    B_ASYNC(0, 0);
    A_LOADS(0);
    cpasync_wait0();
    CONVERT(0, 0);
    __syncthreads();

    for (int c = 0; c < 8; ++c) {
        const int b = c & 1;
        if (c < 7) {
            B_ASYNC(c + 1, b ^ 1);
            A_LOADS(c + 1);
        }

#pragma unroll
        for (int ks = 0; ks < 2; ++ks) {
            uint32_t a_hi[2][4];
#pragma unroll
            for (int im = 0; im < 2; ++im) {
                uint32_t ofs = (uint32_t)(im * 16 * SA + ks * 16) * 2;
                ldsm4(a_hi[im], aHi[b] + ofs);
            }
#pragma unroll
            for (int jp = 0; jp < 4; ++jp) {
                uint32_t b4[4];
                uint32_t ofs = (uint32_t)(ks * 16 * SB + jp * 16) * 2;
                ldsm4t(b4, bHi[b] + ofs);
#pragma unroll
                for (int im = 0; im < 2; ++im) {
                    mma16816(acc[im][jp * 2 + 0], a_hi[im], b4[0], b4[1]);
                    mma16816(acc[im][jp * 2 + 1], a_hi[im], b4[2], b4[3]);
                }
            }
        }

        if (c < 7) {
            cpasync_wait0();
            CONVERT(b ^ 1, b ^ 1);
        }
        __syncthreads();
    }

    // ---- epilogue: regs -> global, + bias (+ residual)
    const int qr = lane >> 2;        // 0..7
    const int qc = (lane & 3) * 2;   // 0,2,4,6
#pragma unroll
    for (int im = 0; im < 2; ++im) {
        int mA = m0 + m0w + im * 16 + qr;
        int mB = mA + 8;
        float bA = bias[mA];
        float bB = bias[mB];
#pragma unroll
        for (int jn = 0; jn < 8; ++jn) {
            int n = l0 + n0w + jn * 8 + qc;
            size_t gA = (size_t)mA * LD + n;
            size_t gB = (size_t)mB * LD + n;
            float o0 = acc[im][jn][0] + bA;
            float o1 = acc[im][jn][1] + bA;
            float o2 = acc[im][jn][2] + bB;
            float o3 = acc[im][jn][3] + bB;
            if (Rn) {
                float2 rA = *(const float2*)(Rn + gA);
                float2 rB = *(const float2*)(Rn + gB);
                o0 += rA.x; o1 += rA.y; o2 += rB.x; o3 += rB.y;
            }
            float2 vA = {o0, o1};
            float2 vB = {o2, o3};
            *(float2*)(Yn + gA) = vA;
            *(float2*)(Yn + gB) = vB;
        }
    }
}

// ---------------------------------------------------------------------------
// K row stats: max and 1/sum(exp(v - max)) per (n, channel) row of g_K.
// ---------------------------------------------------------------------------
__global__ __launch_bounds__(256) void kstats_kernel()
{
    __shared__ float red[256];
    const int row = blockIdx.x;
    const float* r = g_K + (size_t)row * LD;
    const int tid = threadIdx.x;

    float v[25];
    float mx = -1e30f;
#pragma unroll
    for (int i = 0; i < 25; ++i) {
        v[i] = r[tid + i * 256];
        mx = fmaxf(mx, v[i]);
    }
    red[tid] = mx;
    __syncthreads();
    for (int s = 128; s > 0; s >>= 1) {
        if (tid < s) red[tid] = fmaxf(red[tid], red[tid + s]);
        __syncthreads();
    }
    mx = red[0];
    __syncthreads();

    float sm = 0.0f;
#pragma unroll
    for (int i = 0; i < 25; ++i) sm += __expf(v[i] - mx);
    red[tid] = sm;
    __syncthreads();
    for (int s = 128; s > 0; s >>= 1) {
        if (tid < s) red[tid] += red[tid + s];
        __syncthreads();
    }
    if (tid == 0) {
        g_kmax[row] = mx;
        g_kinv[row] = 1.0f / red[0];
    }
}

__global__ void zero_ctx_kernel()
{
    g_CTX[blockIdx.x * 256 + threadIdx.x] = 0.0f;
}

// ---------------------------------------------------------------------------
// context[n,h,kc,vc] = sum_l softmax_L(K)[n,h,kc,l] * V[n,h,vc,l]
// ---------------------------------------------------------------------------
__global__ __launch_bounds__(256) void context_kernel()
{
    __shared__ float sk[32][129];
    __shared__ float sv[32][129];
    const int n = blockIdx.z, h = blockIdx.y;
    const size_t base = (((size_t)n * NHEADS + h) * HC) * LD;
    const int rowbase = n * CD + h * HC;
    const int tid = threadIdx.x;
    const int kc = tid >> 3;
    const int vg = (tid & 7) * 4;

    float acc0 = 0.f, acc1 = 0.f, acc2 = 0.f, acc3 = 0.f;

    for (int t = 0; t < 5; ++t) {
        const int l0 = blockIdx.x * 640 + t * 128;
#pragma unroll
        for (int s = 0; s < 16; s++) {
            int idx = tid + s * 256;
            int c = idx >> 7, l = idx & 127;
            float kraw = g_K[base + (size_t)c * LD + l0 + l];
            sk[c][l] = __expf(kraw - g_kmax[rowbase + c]);
            sv[c][l] = g_V[base + (size_t)c * LD + l0 + l];
        }
        __syncthreads();
#pragma unroll 4
        for (int l = 0; l < 128; l++) {
            float a = sk[kc][l];
            acc0 += a * sv[vg + 0][l];
            acc1 += a * sv[vg + 1][l];
            acc2 += a * sv[vg + 2][l];
            acc3 += a * sv[vg + 3][l];
        }
        __syncthreads();
    }
    float inv = g_kinv[rowbase + kc];
    const size_t cb = (((size_t)n * NHEADS + h) * HC + kc) * HC + vg;
    atomicAdd(&g_CTX[cb + 0], acc0 * inv);
    atomicAdd(&g_CTX[cb + 1], acc1 * inv);
    atomicAdd(&g_CTX[cb + 2], acc2 * inv);
    atomicAdd(&g_CTX[cb + 3], acc3 * inv);
}

// ---------------------------------------------------------------------------
// attended[n,h,vc,l] = sum_kc ctx[n,h,kc,vc] * softmax_C(q)[n,h,kc,l]
// ---------------------------------------------------------------------------
__global__ __launch_bounds__(128) void attend_kernel()
{
    __shared__ float4 sctx[32][8];
    const int n = blockIdx.z, h = blockIdx.y;
    const int tid = threadIdx.x;
    {
        const float4* C = (const float4*)(g_CTX + (((size_t)n * NHEADS + h) * HC) * HC);
#pragma unroll
        for (int s = 0; s < 2; s++) {
            int idx = tid + s * 128;
            sctx[idx >> 3][idx & 7] = C[idx];
        }
    }
    __syncthreads();

    const int l = blockIdx.x * 128 + tid;
    const size_t base = (((size_t)n * NHEADS + h) * HC) * LD + l;

    float q[HC];
    float mx = -1e30f;
#pragma unroll
    for (int c = 0; c < HC; c++) {
        q[c] = g_Q[base + (size_t)c * LD];
        mx = fmaxf(mx, q[c]);
    }
    float s = 0.0f;
#pragma unroll
    for (int c = 0; c < HC; c++) {
        q[c] = __expf(q[c] - mx);
        s += q[c];
    }
    float inv = 1.0f / s;
#pragma unroll
    for (int c = 0; c < HC; c++) q[c] *= inv;

    float acc[HC];
#pragma unroll
    for (int v = 0; v < HC; v++) acc[v] = 0.0f;

#pragma unroll
    for (int kc = 0; kc < HC; kc++) {
        float a = q[kc];
#pragma unroll
        for (int vq = 0; vq < 8; vq++) {
            float4 c4 = sctx[kc][vq];
            acc[vq * 4 + 0] += a * c4.x;
            acc[vq * 4 + 1] += a * c4.y;
            acc[vq * 4 + 2] += a * c4.z;
            acc[vq * 4 + 3] += a * c4.w;
        }
    }
#pragma unroll
    for (int v = 0; v < HC; v++) g_ATT[base + (size_t)v * LD] = acc[v];
}

// ---------------------------------------------------------------------------
extern "C" void kernel_launch(void* const* d_in, const int* in_sizes, int n_in,
                              void* d_out, int out_size)
{
    const float* qf = (const float*)d_in[0];
    const float* kf = (const float*)d_in[1];
    const float* vf = (const float*)d_in[2];
    const float* Wq = (const float*)d_in[3];
    const float* bq = (const float*)d_in[4];
    const float* Wk = (const float*)d_in[5];
    const float* bk = (const float*)d_in[6];
    const float* Wv = (const float*)d_in[7];
    const float* bv = (const float*)d_in[8];
    const float* Wr = (const float*)d_in[9];
    const float* br = (const float*)d_in[10];
    float* out = (float*)d_out;

    float *Q, *K, *V, *ATT;
    cudaGetSymbolAddress((void**)&Q,   g_Q);
    cudaGetSymbolAddress((void**)&K,   g_K);
    cudaGetSymbolAddress((void**)&V,   g_V);
    cudaGetSymbolAddress((void**)&ATT, g_ATT);

    cudaFuncSetAttribute(hmma_gemm_kernel,
                         cudaFuncAttributeMaxDynamicSharedMemorySize, GEMM_SMEM);

    dim3 gemm_grid(LD / 128, CD / 128, NB);   // (50, 2, 8)
    hmma_gemm_kernel<<<gemm_grid, 256, GEMM_SMEM>>>(kf, Wk, bk, nullptr, K);
    hmma_gemm_kernel<<<gemm_grid, 256, GEMM_SMEM>>>(qf, Wq, bq, nullptr, Q);
    hmma_gemm_kernel<<<gemm_grid, 256, GEMM_SMEM>>>(vf, Wv, bv, nullptr, V);

    kstats_kernel<<<NB * CD, 256>>>();
    zero_ctx_kernel<<<(NB * NHEADS * HC * HC) / 256, 256>>>();
    context_kernel<<<dim3(10, NHEADS, NB), 256>>>();
    attend_kernel<<<dim3(LD / 128, NHEADS, NB), 128>>>();

    hmma_gemm_kernel<<<gemm_grid, 256, GEMM_SMEM>>>(ATT, Wr, br, qf, out);
}

// round 7
// speedup vs baseline: 2.4910x; 1.0553x over previous
#include <cuda_runtime.h>
#include <cuda_bf16.h>
#include <cstdint>

#define NB 8
#define CD 256
#define LD 6400
#define NHEADS 8
#define HC 32

// Scratch (device globals -- no allocation allowed)
__device__ float g_Q[NB * CD * LD];
__device__ float g_K[NB * CD * LD];
__device__ float g_V[NB * CD * LD];
__device__ float g_CTX[NB * NHEADS * HC * HC];
__device__ float g_kmax[NB * CD];
__device__ float g_kinv[NB * CD];
__device__ __nv_bfloat16 g_Qbf[NB * CD * LD];
__device__ __nv_bfloat16 g_Kbf[NB * CD * LD];
__device__ __nv_bfloat16 g_Vbf[NB * CD * LD];
__device__ __nv_bfloat16 g_ATTbf[NB * CD * LD];

// ---------------------------------------------------------------------------
// mma.sync / ldmatrix / cp.async helpers (baseline PTX, works on compute_103)
// ---------------------------------------------------------------------------
__device__ __forceinline__ uint32_t smem_u32(const void* p) {
    uint32_t a;
    asm("{ .reg .u64 t; cvta.to.shared.u64 t, %1; cvt.u32.u64 %0, t; }"
        : "=r"(a) : "l"(p));
    return a;
}

__device__ __forceinline__ void ldsm4(uint32_t* r, uint32_t addr) {
    asm volatile("ldmatrix.sync.aligned.m8n8.x4.shared.b16 {%0,%1,%2,%3}, [%4];"
                 : "=r"(r[0]), "=r"(r[1]), "=r"(r[2]), "=r"(r[3]) : "r"(addr));
}
__device__ __forceinline__ void ldsm4t(uint32_t* r, uint32_t addr) {
    asm volatile("ldmatrix.sync.aligned.m8n8.x4.trans.shared.b16 {%0,%1,%2,%3}, [%4];"
                 : "=r"(r[0]), "=r"(r[1]), "=r"(r[2]), "=r"(r[3]) : "r"(addr));
}

__device__ __forceinline__ void mma16816(float* c, const uint32_t* a,
                                         uint32_t b0, uint32_t b1) {
    asm volatile(
        "mma.sync.aligned.m16n8k16.row.col.f32.bf16.bf16.f32 "
        "{%0,%1,%2,%3}, {%4,%5,%6,%7}, {%8,%9}, {%0,%1,%2,%3};"
        : "+f"(c[0]), "+f"(c[1]), "+f"(c[2]), "+f"(c[3])
        : "r"(a[0]), "r"(a[1]), "r"(a[2]), "r"(a[3]), "r"(b0), "r"(b1));
}

__device__ __forceinline__ void cpasync16(uint32_t saddr, const void* g) {
    asm volatile("cp.async.cg.shared.global [%0], [%1], 16;"
                 :: "r"(saddr), "l"(g) : "memory");
}
__device__ __forceinline__ void cpasync_commit() {
    asm volatile("cp.async.commit_group;" ::: "memory");
}
__device__ __forceinline__ void cpasync_wait0() {
    asm volatile("cp.async.wait_group 0;" ::: "memory");
}

// ---------------------------------------------------------------------------
// fp32 -> bf16 conversion kernel (grid-stride, float4 -> 4x bf16)
// ---------------------------------------------------------------------------
__global__ __launch_bounds__(256) void cvt_bf16_kernel(
    const float* __restrict__ src, __nv_bfloat16* __restrict__ dst)
{
    const size_t N4 = (size_t)NB * CD * LD / 4;
    const float4* s4 = (const float4*)src;
    size_t i = (size_t)blockIdx.x * 256 + threadIdx.x;
    const size_t stride = (size_t)gridDim.x * 256;
    for (; i < N4; i += stride) {
        float4 v = s4[i];
        union { __nv_bfloat162 h[2]; unsigned long long u; } u;
        u.h[0] = __float22bfloat162_rn(make_float2(v.x, v.y));
        u.h[1] = __float22bfloat162_rn(make_float2(v.z, v.w));
        *(unsigned long long*)&dst[i * 4] = u.u;
    }
}

// ---------------------------------------------------------------------------
// HMMA GEMM: Y[n, m, l] = sum_k W[m,k] * Xbf[n,k,l] + bias[m] (+ resid)
// Block tile 128(m) x 128(l), BK=32, 8 warps (warp tile 32x64).
// B already bf16 in gmem -> cp.async directly into swizzle-padded smem.
// ---------------------------------------------------------------------------
#define SA 40    // bf16 stride of A smem rows (80B -> conflict-free ldmatrix)
#define SB 136   // bf16 stride of B smem rows (272B -> conflict-free ldmatrix)
#define ELA (128 * SA)           // 5120 bf16
#define ELB (32 * SB)            // 4352 bf16
#define BUFEL (ELA + ELB)        // per-buffer elements (9472)
#define GEMM_SMEM (2 * BUFEL * 2)  // 37888 bytes

__global__ __launch_bounds__(256, 2) void hmma_gemm_kernel(
    const __nv_bfloat16* __restrict__ X, const float* __restrict__ W,
    const float* __restrict__ bias, const float* __restrict__ resid,
    float* __restrict__ Y)
{
    extern __shared__ __align__(16) __nv_bfloat16 dsm[];

    const int tid  = threadIdx.x;
    const int wid  = tid >> 5;
    const int lane = tid & 31;
    const int l0   = blockIdx.x * 128;
    const int m0   = blockIdx.y * 128;
    const int nb   = blockIdx.z;

    const int m0w = (wid & 3) * 32;   // warp m offset in block
    const int n0w = (wid >> 2) * 64;  // warp n offset in block

    const __nv_bfloat16* Xn = X + (size_t)nb * CD * LD;
    float* Yn = Y + (size_t)nb * CD * LD;
    const float* Rn = resid ? resid + (size_t)nb * CD * LD : nullptr;

    float acc[2][8][4];
#pragma unroll
    for (int i = 0; i < 2; i++)
#pragma unroll
        for (int j = 0; j < 8; j++)
#pragma unroll
            for (int e = 0; e < 4; e++) acc[i][j][e] = 0.0f;

    // ldmatrix lane address bases, per buffer
    const int a_tile = lane >> 3;
    const int a_row  = m0w + ((a_tile & 1) << 3) + (lane & 7);
    const int a_koff = (a_tile >> 1) << 3;
    const int b_k = lane & 15;
    const int b_n = n0w + ((lane >> 4) << 3);

    uint32_t aHi[2], bHi[2];
    __nv_bfloat16* Abuf[2];
    uint32_t bSt[2];
    // cp.async mapping: tid -> (k = tid>>4, lq = tid&15), 2 iters (k+16)
    const int st_k  = tid >> 4;        // 0..15
    const int st_lq = tid & 15;        // 16B chunk index (8 bf16 each)
#pragma unroll
    for (int b = 0; b < 2; ++b) {
        __nv_bfloat16* A  = dsm + b * BUFEL;
        __nv_bfloat16* BH = A + ELA;
        Abuf[b] = A;
        aHi[b] = smem_u32(&A[a_row * SA + a_koff]);
        bHi[b] = smem_u32(&BH[b_k * SB + b_n]);
        bSt[b] = smem_u32(&BH[st_k * SB + st_lq * 8]);
    }

    const float4* W4 = (const float4*)W;

    float4 av[4];

#define B_ASYNC(c, sb)                                                         \
    {                                                                          \
        _Pragma("unroll")                                                      \
        for (int i = 0; i < 2; ++i) {                                          \
            const __nv_bfloat16* g =                                           \
                Xn + (size_t)((c) * 32 + st_k + i * 16) * LD + l0 + st_lq * 8; \
            cpasync16(bSt[sb] + (uint32_t)(i * 16 * SB * 2), g);               \
        }                                                                      \
        cpasync_commit();                                                      \
    }

#define A_LOADS(c)                                                             \
    {                                                                          \
        _Pragma("unroll")                                                      \
        for (int i = 0; i < 4; ++i) {                                          \
            int f4  = tid + i * 256;                                           \
            int row = f4 >> 3;                                                 \
            int kq  = f4 & 7;                                                  \
            av[i] = W4[(size_t)(m0 + row) * 64 + (c) * 8 + kq];                \
        }                                                                      \
    }

#define A_STORES(b)                                                            \
    {                                                                          \
        _Pragma("unroll")                                                      \
        for (int i = 0; i < 4; ++i) {                                          \
            int f4  = tid + i * 256;                                           \
            int row = f4 >> 3;                                                 \
            int kq  = f4 & 7;                                                  \
            union { __nv_bfloat162 h[2]; unsigned long long u; } ua;           \
            ua.h[0] = __float22bfloat162_rn(make_float2(av[i].x, av[i].y));    \
            ua.h[1] = __float22bfloat162_rn(make_float2(av[i].z, av[i].w));    \
            *(unsigned long long*)&Abuf[b][row * SA + kq * 4] = ua.u;          \
        }                                                                      \
    }

    // prologue: chunk 0
    B_ASYNC(0, 0);
    A_LOADS(0);
    A_STORES(0);
    cpasync_wait0();
    __syncthreads();

    for (int c = 0; c < 8; ++c) {
        const int b = c & 1;
        if (c < 7) {
            B_ASYNC(c + 1, b ^ 1);
            A_LOADS(c + 1);
        }

#pragma unroll
        for (int ks = 0; ks < 2; ++ks) {
            uint32_t a_hi[2][4];
#pragma unroll
            for (int im = 0; im < 2; ++im) {
                uint32_t ofs = (uint32_t)(im * 16 * SA + ks * 16) * 2;
                ldsm4(a_hi[im], aHi[b] + ofs);
            }
#pragma unroll
            for (int jp = 0; jp < 4; ++jp) {
                uint32_t b4[4];
                uint32_t ofs = (uint32_t)(ks * 16 * SB + jp * 16) * 2;
                ldsm4t(b4, bHi[b] + ofs);
#pragma unroll
                for (int im = 0; im < 2; ++im) {
                    mma16816(acc[im][jp * 2 + 0], a_hi[im], b4[0], b4[1]);
                    mma16816(acc[im][jp * 2 + 1], a_hi[im], b4[2], b4[3]);
                }
            }
        }

        if (c < 7) {
            A_STORES(b ^ 1);
            cpasync_wait0();
        }
        __syncthreads();
    }

    // ---- epilogue: regs -> global, + bias (+ residual)
    const int qr = lane >> 2;        // 0..7
    const int qc = (lane & 3) * 2;   // 0,2,4,6
#pragma unroll
    for (int im = 0; im < 2; ++im) {
        int mA = m0 + m0w + im * 16 + qr;
        int mB = mA + 8;
        float bA = bias[mA];
        float bB = bias[mB];
#pragma unroll
        for (int jn = 0; jn < 8; ++jn) {
            int n = l0 + n0w + jn * 8 + qc;
            size_t gA = (size_t)mA * LD + n;
            size_t gB = (size_t)mB * LD + n;
            float o0 = acc[im][jn][0] + bA;
            float o1 = acc[im][jn][1] + bA;
            float o2 = acc[im][jn][2] + bB;
            float o3 = acc[im][jn][3] + bB;
            if (Rn) {
                float2 rA = *(const float2*)(Rn + gA);
                float2 rB = *(const float2*)(Rn + gB);
                o0 += rA.x; o1 += rA.y; o2 += rB.x; o3 += rB.y;
            }
            float2 vA = {o0, o1};
            float2 vB = {o2, o3};
            *(float2*)(Yn + gA) = vA;
            *(float2*)(Yn + gB) = vB;
        }
    }
}

// ---------------------------------------------------------------------------
// K row stats: max and 1/sum(exp(v - max)) per (n, channel) row of g_K.
// ---------------------------------------------------------------------------
__global__ __launch_bounds__(256) void kstats_kernel()
{
    __shared__ float red[256];
    const int row = blockIdx.x;
    const float* r = g_K + (size_t)row * LD;
    const int tid = threadIdx.x;

    float v[25];
    float mx = -1e30f;
#pragma unroll
    for (int i = 0; i < 25; ++i) {
        v[i] = r[tid + i * 256];
        mx = fmaxf(mx, v[i]);
    }
    red[tid] = mx;
    __syncthreads();
    for (int s = 128; s > 0; s >>= 1) {
        if (tid < s) red[tid] = fmaxf(red[tid], red[tid + s]);
        __syncthreads();
    }
    mx = red[0];
    __syncthreads();

    float sm = 0.0f;
#pragma unroll
    for (int i = 0; i < 25; ++i) sm += __expf(v[i] - mx);
    red[tid] = sm;
    __syncthreads();
    for (int s = 128; s > 0; s >>= 1) {
        if (tid < s) red[tid] += red[tid + s];
        __syncthreads();
    }
    if (tid == 0) {
        g_kmax[row] = mx;
        g_kinv[row] = 1.0f / red[0];
    }
}

__global__ void zero_ctx_kernel()
{
    g_CTX[blockIdx.x * 256 + threadIdx.x] = 0.0f;
}

// ---------------------------------------------------------------------------
// context[n,h,kc,vc] = sum_l softmax_L(K)[n,h,kc,l] * V[n,h,vc,l]
// ---------------------------------------------------------------------------
__global__ __launch_bounds__(256) void context_kernel()
{
    __shared__ float sk[32][129];
    __shared__ float sv[32][129];
    const int n = blockIdx.z, h = blockIdx.y;
    const size_t base = (((size_t)n * NHEADS + h) * HC) * LD;
    const int rowbase = n * CD + h * HC;
    const int tid = threadIdx.x;
    const int kc = tid >> 3;
    const int vg = (tid & 7) * 4;

    float acc0 = 0.f, acc1 = 0.f, acc2 = 0.f, acc3 = 0.f;

    for (int t = 0; t < 5; ++t) {
        const int l0 = blockIdx.x * 640 + t * 128;
#pragma unroll
        for (int s = 0; s < 16; s++) {
            int idx = tid + s * 256;
            int c = idx >> 7, l = idx & 127;
            float kraw = g_K[base + (size_t)c * LD + l0 + l];
            sk[c][l] = __expf(kraw - g_kmax[rowbase + c]);
            sv[c][l] = g_V[base + (size_t)c * LD + l0 + l];
        }
        __syncthreads();
#pragma unroll 4
        for (int l = 0; l < 128; l++) {
            float a = sk[kc][l];
            acc0 += a * sv[vg + 0][l];
            acc1 += a * sv[vg + 1][l];
            acc2 += a * sv[vg + 2][l];
            acc3 += a * sv[vg + 3][l];
        }
        __syncthreads();
    }
    float inv = g_kinv[rowbase + kc];
    const size_t cb = (((size_t)n * NHEADS + h) * HC + kc) * HC + vg;
    atomicAdd(&g_CTX[cb + 0], acc0 * inv);
    atomicAdd(&g_CTX[cb + 1], acc1 * inv);
    atomicAdd(&g_CTX[cb + 2], acc2 * inv);
    atomicAdd(&g_CTX[cb + 3], acc3 * inv);
}

// ---------------------------------------------------------------------------
// attended[n,h,vc,l] = sum_kc ctx[n,h,kc,vc] * softmax_C(q)[n,h,kc,l]
// Writes bf16 directly for the recovery GEMM.
// ---------------------------------------------------------------------------
__global__ __launch_bounds__(128) void attend_kernel()
{
    __shared__ float4 sctx[32][8];
    const int n = blockIdx.z, h = blockIdx.y;
    const int tid = threadIdx.x;
    {
        const float4* C = (const float4*)(g_CTX + (((size_t)n * NHEADS + h) * HC) * HC);
#pragma unroll
        for (int s = 0; s < 2; s++) {
            int idx = tid + s * 128;
            sctx[idx >> 3][idx & 7] = C[idx];
        }
    }
    __syncthreads();

    const int l = blockIdx.x * 128 + tid;
    const size_t base = (((size_t)n * NHEADS + h) * HC) * LD + l;

    float q[HC];
    float mx = -1e30f;
#pragma unroll
    for (int c = 0; c < HC; c++) {
        q[c] = g_Q[base + (size_t)c * LD];
        mx = fmaxf(mx, q[c]);
    }
    float s = 0.0f;
#pragma unroll
    for (int c = 0; c < HC; c++) {
        q[c] = __expf(q[c] - mx);
        s += q[c];
    }
    float inv = 1.0f / s;
#pragma unroll
    for (int c = 0; c < HC; c++) q[c] *= inv;

    float acc[HC];
#pragma unroll
    for (int v = 0; v < HC; v++) acc[v] = 0.0f;

#pragma unroll
    for (int kc = 0; kc < HC; kc++) {
        float a = q[kc];
#pragma unroll
        for (int vq = 0; vq < 8; vq++) {
            float4 c4 = sctx[kc][vq];
            acc[vq * 4 + 0] += a * c4.x;
            acc[vq * 4 + 1] += a * c4.y;
            acc[vq * 4 + 2] += a * c4.z;
            acc[vq * 4 + 3] += a * c4.w;
        }
    }
#pragma unroll
    for (int v = 0; v < HC; v++)
        g_ATTbf[base + (size_t)v * LD] = __float2bfloat16(acc[v]);
}

// ---------------------------------------------------------------------------
extern "C" void kernel_launch(void* const* d_in, const int* in_sizes, int n_in,
                              void* d_out, int out_size)
{
    const float* qf = (const float*)d_in[0];
    const float* kf = (const float*)d_in[1];
    const float* vf = (const float*)d_in[2];
    const float* Wq = (const float*)d_in[3];
    const float* bq = (const float*)d_in[4];
    const float* Wk = (const float*)d_in[5];
    const float* bk = (const float*)d_in[6];
    const float* Wv = (const float*)d_in[7];
    const float* bv = (const float*)d_in[8];
    const float* Wr = (const float*)d_in[9];
    const float* br = (const float*)d_in[10];
    float* out = (float*)d_out;

    float *Q, *K, *V;
    __nv_bfloat16 *Qbf, *Kbf, *Vbf, *ATTbf;
    cudaGetSymbolAddress((void**)&Q,     g_Q);
    cudaGetSymbolAddress((void**)&K,     g_K);
    cudaGetSymbolAddress((void**)&V,     g_V);
    cudaGetSymbolAddress((void**)&Qbf,   g_Qbf);
    cudaGetSymbolAddress((void**)&Kbf,   g_Kbf);
    cudaGetSymbolAddress((void**)&Vbf,   g_Vbf);
    cudaGetSymbolAddress((void**)&ATTbf, g_ATTbf);

    cudaFuncSetAttribute(hmma_gemm_kernel,
                         cudaFuncAttributeMaxDynamicSharedMemorySize, GEMM_SMEM);

    dim3 gemm_grid(LD / 128, CD / 128, NB);   // (50, 2, 8)

    cvt_bf16_kernel<<<2048, 256>>>(kf, Kbf);                               // 1
    cvt_bf16_kernel<<<2048, 256>>>(qf, Qbf);                               // 2
    cvt_bf16_kernel<<<2048, 256>>>(vf, Vbf);                               // 3
    hmma_gemm_kernel<<<gemm_grid, 256, GEMM_SMEM>>>(Kbf, Wk, bk, nullptr, K); // 4 (ncu)
    hmma_gemm_kernel<<<gemm_grid, 256, GEMM_SMEM>>>(Qbf, Wq, bq, nullptr, Q); // 5
    hmma_gemm_kernel<<<gemm_grid, 256, GEMM_SMEM>>>(Vbf, Wv, bv, nullptr, V); // 6

    kstats_kernel<<<NB * CD, 256>>>();                                     // 7
    zero_ctx_kernel<<<(NB * NHEADS * HC * HC) / 256, 256>>>();             // 8
    context_kernel<<<dim3(10, NHEADS, NB), 256>>>();                       // 9
    attend_kernel<<<dim3(LD / 128, NHEADS, NB), 128>>>();                  // 10

    hmma_gemm_kernel<<<gemm_grid, 256, GEMM_SMEM>>>(ATTbf, Wr, br, qf, out); // 11
}

// round 9
// speedup vs baseline: 2.6082x; 1.0470x over previous
#include <cuda_runtime.h>
#include <cuda_bf16.h>
#include <cstdint>

#define NB 8
#define CD 256
#define LD 6400
#define NHEADS 8
#define HC 32

// Scratch (device globals -- no allocation allowed)
__device__ float g_Q[NB * CD * LD];
__device__ float g_K[NB * CD * LD];
__device__ float g_V[NB * CD * LD];
__device__ float g_CTX[NB * NHEADS * HC * HC];
__device__ float g_kmax[NB * CD];
__device__ float g_kinv[NB * CD];
__device__ __nv_bfloat16 g_Qbf[NB * CD * LD];
__device__ __nv_bfloat16 g_Kbf[NB * CD * LD];
__device__ __nv_bfloat16 g_Vbf[NB * CD * LD];
__device__ __nv_bfloat16 g_ATTbf[NB * CD * LD];
__device__ __nv_bfloat16 g_Wt[4 * 256 * 256];   // k-major bf16: Wq,Wk,Wv,Wr

// ---------------------------------------------------------------------------
// mma.sync / ldmatrix / cp.async helpers (baseline PTX, works on compute_103)
// ---------------------------------------------------------------------------
__device__ __forceinline__ uint32_t smem_u32(const void* p) {
    uint32_t a;
    asm("{ .reg .u64 t; cvta.to.shared.u64 t, %1; cvt.u32.u64 %0, t; }"
        : "=r"(a) : "l"(p));
    return a;
}

__device__ __forceinline__ void ldsm4t(uint32_t* r, uint32_t addr) {
    asm volatile("ldmatrix.sync.aligned.m8n8.x4.trans.shared.b16 {%0,%1,%2,%3}, [%4];"
                 : "=r"(r[0]), "=r"(r[1]), "=r"(r[2]), "=r"(r[3]) : "r"(addr));
}

__device__ __forceinline__ void mma16816(float* c, uint32_t a0, uint32_t a1,
                                         uint32_t a2, uint32_t a3,
                                         uint32_t b0, uint32_t b1) {
    asm volatile(
        "mma.sync.aligned.m16n8k16.row.col.f32.bf16.bf16.f32 "
        "{%0,%1,%2,%3}, {%4,%5,%6,%7}, {%8,%9}, {%0,%1,%2,%3};"
        : "+f"(c[0]), "+f"(c[1]), "+f"(c[2]), "+f"(c[3])
        : "r"(a0), "r"(a1), "r"(a2), "r"(a3), "r"(b0), "r"(b1));
}

__device__ __forceinline__ void cpasync16(uint32_t saddr, const void* g) {
    asm volatile("cp.async.cg.shared.global [%0], [%1], 16;"
                 :: "r"(saddr), "l"(g) : "memory");
}
__device__ __forceinline__ void cpasync_commit() {
    asm volatile("cp.async.commit_group;" ::: "memory");
}
__device__ __forceinline__ void cpasync_wait0() {
    asm volatile("cp.async.wait_group 0;" ::: "memory");
}
__device__ __forceinline__ void cpasync_wait1() {
    asm volatile("cp.async.wait_group 1;" ::: "memory");
}

// ---------------------------------------------------------------------------
// fp32 -> bf16 conversion kernel (grid-stride, float4 -> 4x bf16)
// ---------------------------------------------------------------------------
__global__ __launch_bounds__(256) void cvt_bf16_kernel(
    const float* __restrict__ src, __nv_bfloat16* __restrict__ dst)
{
    const size_t N4 = (size_t)NB * CD * LD / 4;
    const float4* s4 = (const float4*)src;
    size_t i = (size_t)blockIdx.x * 256 + threadIdx.x;
    const size_t stride = (size_t)gridDim.x * 256;
    for (; i < N4; i += stride) {
        float4 v = s4[i];
        union { __nv_bfloat162 h[2]; unsigned long long u; } u;
        u.h[0] = __float22bfloat162_rn(make_float2(v.x, v.y));
        u.h[1] = __float22bfloat162_rn(make_float2(v.z, v.w));
        *(unsigned long long*)&dst[i * 4] = u.u;
    }
}

// ---------------------------------------------------------------------------
// V conversion + W transposes (Wq,Wk,Wv,Wr -> k-major bf16) in one launch.
// Blocks [0,2048): convert V.  Blocks [2048,2112): transpose the 4 W's.
// ---------------------------------------------------------------------------
__global__ __launch_bounds__(256) void cvt_vw_kernel(
    const float* __restrict__ src, __nv_bfloat16* __restrict__ dst,
    const float* __restrict__ Wq, const float* __restrict__ Wk,
    const float* __restrict__ Wv, const float* __restrict__ Wr)
{
    if (blockIdx.x < 2048) {
        const size_t N4 = (size_t)NB * CD * LD / 4;
        const float4* s4 = (const float4*)src;
        size_t i = (size_t)blockIdx.x * 256 + threadIdx.x;
        const size_t stride = (size_t)2048 * 256;
        for (; i < N4; i += stride) {
            float4 v = s4[i];
            union { __nv_bfloat162 h[2]; unsigned long long u; } u;
            u.h[0] = __float22bfloat162_rn(make_float2(v.x, v.y));
            u.h[1] = __float22bfloat162_rn(make_float2(v.z, v.w));
            *(unsigned long long*)&dst[i * 4] = u.u;
        }
    } else {
        int t = (blockIdx.x - 2048) * 256 + threadIdx.x;   // 0..16383
        const float* Ws[4] = {Wq, Wk, Wv, Wr};
#pragma unroll
        for (int w = 0; w < 4; ++w) {
            const float* W = Ws[w];
            __nv_bfloat16* D = g_Wt + w * 65536;
            for (int idx = t; idx < 65536; idx += 16384) {
                int m = idx >> 8, k = idx & 255;
                D[k * 256 + m] = __float2bfloat16(W[idx]);   // W[m*256+k]
            }
        }
    }
}

// ---------------------------------------------------------------------------
// HMMA GEMM: Y[n, m, l] = sum_k Wt[k,m] * Xbf[n,k,l] + bias[m] (+ resid)
// Block tile 128(m) x 128(l), BK=32, 8 warps (warp tile 32x64).
// Both operands bf16 k-major in smem -> cp.async direct, ldsm4t both sides.
// 3-stage cp.async pipeline. Fused Q/K/V via blockIdx.z (proj = z>>3).
// ---------------------------------------------------------------------------
#define SB 136                     // bf16 row stride (272B, conflict-free ldsm)
#define REG_EL (32 * SB)           // 4352 bf16 per operand region
#define STAGE_BYTES (2 * REG_EL * 2)   // A + B regions = 17408 bytes
#define GEMM_SMEM (3 * STAGE_BYTES)    // 52224 bytes

__global__ __launch_bounds__(256, 2) void hmma_gemm_kernel(
    const __nv_bfloat16* __restrict__ X0, const __nv_bfloat16* __restrict__ X1,
    const __nv_bfloat16* __restrict__ X2,
    const __nv_bfloat16* __restrict__ Wt0, const __nv_bfloat16* __restrict__ Wt1,
    const __nv_bfloat16* __restrict__ Wt2,
    const float* __restrict__ b0p, const float* __restrict__ b1p,
    const float* __restrict__ b2p,
    float* __restrict__ Y0, float* __restrict__ Y1, float* __restrict__ Y2,
    const float* __restrict__ resid)
{
    extern __shared__ __align__(16) __nv_bfloat16 dsm[];

    const int tid  = threadIdx.x;
    const int wid  = tid >> 5;
    const int lane = tid & 31;
    const int l0   = blockIdx.x * 128;
    const int m0   = blockIdx.y * 128;
    const int proj = blockIdx.z >> 3;
    const int nb   = blockIdx.z & 7;

    const __nv_bfloat16* X;
    const __nv_bfloat16* Wt;
    const float* bias;
    float* Y;
    if (proj == 0)      { X = X0; Wt = Wt0; bias = b0p; Y = Y0; }
    else if (proj == 1) { X = X1; Wt = Wt1; bias = b1p; Y = Y1; }
    else                { X = X2; Wt = Wt2; bias = b2p; Y = Y2; }

    const int m0w = (wid & 3) * 32;   // warp m offset in block
    const int n0w = (wid >> 2) * 64;  // warp n offset in block

    const __nv_bfloat16* Xn = X + (size_t)nb * CD * LD;
    float* Yn = Y + (size_t)nb * CD * LD;
    const float* Rn = resid ? resid + (size_t)nb * CD * LD : nullptr;

    float acc[2][8][4];
#pragma unroll
    for (int i = 0; i < 2; i++)
#pragma unroll
        for (int j = 0; j < 8; j++)
#pragma unroll
            for (int e = 0; e < 4; e++) acc[i][j][e] = 0.0f;

    const uint32_t smBase = smem_u32(dsm);
    // cp.async per-thread chunk offset (same pattern for A and B regions)
    const uint32_t chunk = (uint32_t)((tid >> 4) * (SB * 2) + (tid & 15) * 16);
    // ldsm lane offsets
    const uint32_t aOff = (uint32_t)((lane & 15) * (SB * 2) +
                                     (m0w + ((lane >> 4) << 3)) * 2);
    const uint32_t bOff = (uint32_t)((lane & 15) * (SB * 2) +
                                     (n0w + ((lane >> 4) << 3)) * 2);
    const int g_k  = tid >> 4;    // 0..15
    const int g_c8 = (tid & 15) * 8;

#define ISSUE(c)                                                               \
    {                                                                          \
        uint32_t sb = smBase + ((c) % 3) * STAGE_BYTES;                        \
        const __nv_bfloat16* gA = Wt + ((c) * 32 + g_k) * 256 + m0 + g_c8;     \
        cpasync16(sb + chunk, gA);                                             \
        cpasync16(sb + chunk + 16 * SB * 2, gA + 16 * 256);                    \
        const __nv_bfloat16* gB =                                              \
            Xn + (size_t)((c) * 32 + g_k) * LD + l0 + g_c8;                    \
        cpasync16(sb + 2 * REG_EL + chunk, gB);                                \
        cpasync16(sb + 2 * REG_EL + chunk + 16 * SB * 2, gB + (size_t)16 * LD);\
        cpasync_commit();                                                      \
    }

    ISSUE(0);
    ISSUE(1);

#pragma unroll
    for (int c = 0; c < 8; ++c) {
        if (c < 7) cpasync_wait1(); else cpasync_wait0();
        __syncthreads();
        if (c < 6) ISSUE(c + 2);

        uint32_t aA = smBase + (c % 3) * STAGE_BYTES + aOff;
        uint32_t bA = aA - aOff + 2 * REG_EL + bOff;
#pragma unroll
        for (int ks = 0; ks < 2; ++ks) {
            uint32_t a4[2][4];
#pragma unroll
            for (int im = 0; im < 2; ++im)
                ldsm4t(a4[im], aA + (uint32_t)(ks * 16 * SB * 2 + im * 32));
#pragma unroll
            for (int jp = 0; jp < 4; ++jp) {
                uint32_t b4[4];
                ldsm4t(b4, bA + (uint32_t)(ks * 16 * SB * 2 + jp * 32));
#pragma unroll
                for (int im = 0; im < 2; ++im) {
                    // A fragment from transposed ldsm: {r0, r2, r1, r3}
                    mma16816(acc[im][jp * 2 + 0], a4[im][0], a4[im][2],
                             a4[im][1], a4[im][3], b4[0], b4[1]);
                    mma16816(acc[im][jp * 2 + 1], a4[im][0], a4[im][2],
                             a4[im][1], a4[im][3], b4[2], b4[3]);
                }
            }
        }
    }

    // ---- epilogue: regs -> global, + bias (+ residual)
    const int qr = lane >> 2;        // 0..7
    const int qc = (lane & 3) * 2;   // 0,2,4,6
#pragma unroll
    for (int im = 0; im < 2; ++im) {
        int mA = m0 + m0w + im * 16 + qr;
        int mB = mA + 8;
        float bA = bias[mA];
        float bB = bias[mB];
#pragma unroll
        for (int jn = 0; jn < 8; ++jn) {
            int n = l0 + n0w + jn * 8 + qc;
            size_t gA = (size_t)mA * LD + n;
            size_t gB = (size_t)mB * LD + n;
            float o0 = acc[im][jn][0] + bA;
            float o1 = acc[im][jn][1] + bA;
            float o2 = acc[im][jn][2] + bB;
            float o3 = acc[im][jn][3] + bB;
            if (Rn) {
                float2 rA = *(const float2*)(Rn + gA);
                float2 rB = *(const float2*)(Rn + gB);
                o0 += rA.x; o1 += rA.y; o2 += rB.x; o3 += rB.y;
            }
            float2 vA = {o0, o1};
            float2 vB = {o2, o3};
            *(float2*)(Yn + gA) = vA;
            *(float2*)(Yn + gB) = vB;
        }
    }
}

// ---------------------------------------------------------------------------
// K row stats: max and 1/sum(exp(v - max)) per (n, channel) row of g_K.
// ---------------------------------------------------------------------------
__global__ __launch_bounds__(256) void kstats_kernel()
{
    __shared__ float red[256];
    const int row = blockIdx.x;
    const float* r = g_K + (size_t)row * LD;
    const int tid = threadIdx.x;

    float v[25];
    float mx = -1e30f;
#pragma unroll
    for (int i = 0; i < 25; ++i) {
        v[i] = r[tid + i * 256];
        mx = fmaxf(mx, v[i]);
    }
    red[tid] = mx;
    __syncthreads();
    for (int s = 128; s > 0; s >>= 1) {
        if (tid < s) red[tid] = fmaxf(red[tid], red[tid + s]);
        __syncthreads();
    }
    mx = red[0];
    __syncthreads();

    float sm = 0.0f;
#pragma unroll
    for (int i = 0; i < 25; ++i) sm += __expf(v[i] - mx);
    red[tid] = sm;
    __syncthreads();
    for (int s = 128; s > 0; s >>= 1) {
        if (tid < s) red[tid] += red[tid + s];
        __syncthreads();
    }
    if (tid == 0) {
        g_kmax[row] = mx;
        g_kinv[row] = 1.0f / red[0];
    }
}

__global__ void zero_ctx_kernel()
{
    g_CTX[blockIdx.x * 256 + threadIdx.x] = 0.0f;
}

// ---------------------------------------------------------------------------
// context[n,h,kc,vc] = sum_l softmax_L(K)[n,h,kc,l] * V[n,h,vc,l]
// ---------------------------------------------------------------------------
__global__ __launch_bounds__(256) void context_kernel()
{
    __shared__ float sk[32][129];
    __shared__ float sv[32][129];
    const int n = blockIdx.z, h = blockIdx.y;
    const size_t base = (((size_t)n * NHEADS + h) * HC) * LD;
    const int rowbase = n * CD + h * HC;
    const int tid = threadIdx.x;
    const int kc = tid >> 3;
    const int vg = (tid & 7) * 4;

    float acc0 = 0.f, acc1 = 0.f, acc2 = 0.f, acc3 = 0.f;

    for (int t = 0; t < 5; ++t) {
        const int l0 = blockIdx.x * 640 + t * 128;
#pragma unroll
        for (int s = 0; s < 16; s++) {
            int idx = tid + s * 256;
            int c = idx >> 7, l = idx & 127;
            float kraw = g_K[base + (size_t)c * LD + l0 + l];
            sk[c][l] = __expf(kraw - g_kmax[rowbase + c]);
            sv[c][l] = g_V[base + (size_t)c * LD + l0 + l];
        }
        __syncthreads();
#pragma unroll 4
        for (int l = 0; l < 128; l++) {
            float a = sk[kc][l];
            acc0 += a * sv[vg + 0][l];
            acc1 += a * sv[vg + 1][l];
            acc2 += a * sv[vg + 2][l];
            acc3 += a * sv[vg + 3][l];
        }
        __syncthreads();
    }
    float inv = g_kinv[rowbase + kc];
    const size_t cb = (((size_t)n * NHEADS + h) * HC + kc) * HC + vg;
    atomicAdd(&g_CTX[cb + 0], acc0 * inv);
    atomicAdd(&g_CTX[cb + 1], acc1 * inv);
    atomicAdd(&g_CTX[cb + 2], acc2 * inv);
    atomicAdd(&g_CTX[cb + 3], acc3 * inv);
}

// ---------------------------------------------------------------------------
// attended[n,h,vc,l] = sum_kc ctx[n,h,kc,vc] * softmax_C(q)[n,h,kc,l]
// Writes bf16 directly for the recovery GEMM.
// ---------------------------------------------------------------------------
__global__ __launch_bounds__(128) void attend_kernel()
{
    __shared__ float4 sctx[32][8];
    const int n = blockIdx.z, h = blockIdx.y;
    const int tid = threadIdx.x;
    {
        const float4* C = (const float4*)(g_CTX + (((size_t)n * NHEADS + h) * HC) * HC);
#pragma unroll
        for (int s = 0; s < 2; s++) {
            int idx = tid + s * 128;
            sctx[idx >> 3][idx & 7] = C[idx];
        }
    }
    __syncthreads();

    const int l = blockIdx.x * 128 + tid;
    const size_t base = (((size_t)n * NHEADS + h) * HC) * LD + l;

    float q[HC];
    float mx = -1e30f;
#pragma unroll
    for (int c = 0; c < HC; c++) {
        q[c] = g_Q[base + (size_t)c * LD];
        mx = fmaxf(mx, q[c]);
    }
    float s = 0.0f;
#pragma unroll
    for (int c = 0; c < HC; c++) {
        q[c] = __expf(q[c] - mx);
        s += q[c];
    }
    float inv = 1.0f / s;
#pragma unroll
    for (int c = 0; c < HC; c++) q[c] *= inv;

    float acc[HC];
#pragma unroll
    for (int v = 0; v < HC; v++) acc[v] = 0.0f;

#pragma unroll
    for (int kc = 0; kc < HC; kc++) {
        float a = q[kc];
#pragma unroll
        for (int vq = 0; vq < 8; vq++) {
            float4 c4 = sctx[kc][vq];
            acc[vq * 4 + 0] += a * c4.x;
            acc[vq * 4 + 1] += a * c4.y;
            acc[vq * 4 + 2] += a * c4.z;
            acc[vq * 4 + 3] += a * c4.w;
        }
    }
#pragma unroll
    for (int v = 0; v < HC; v++)
        g_ATTbf[base + (size_t)v * LD] = __float2bfloat16(acc[v]);
}

// ---------------------------------------------------------------------------
extern "C" void kernel_launch(void* const* d_in, const int* in_sizes, int n_in,
                              void* d_out, int out_size)
{
    const float* qf = (const float*)d_in[0];
    const float* kf = (const float*)d_in[1];
    const float* vf = (const float*)d_in[2];
    const float* Wq = (const float*)d_in[3];
    const float* bq = (const float*)d_in[4];
    const float* Wk = (const float*)d_in[5];
    const float* bk = (const float*)d_in[6];
    const float* Wv = (const float*)d_in[7];
    const float* bv = (const float*)d_in[8];
    const float* Wr = (const float*)d_in[9];
    const float* br = (const float*)d_in[10];
    float* out = (float*)d_out;

    float *Q, *K, *V;
    __nv_bfloat16 *Qbf, *Kbf, *Vbf, *ATTbf, *Wt;
    cudaGetSymbolAddress((void**)&Q,     g_Q);
    cudaGetSymbolAddress((void**)&K,     g_K);
    cudaGetSymbolAddress((void**)&V,     g_V);
    cudaGetSymbolAddress((void**)&Qbf,   g_Qbf);
    cudaGetSymbolAddress((void**)&Kbf,   g_Kbf);
    cudaGetSymbolAddress((void**)&Vbf,   g_Vbf);
    cudaGetSymbolAddress((void**)&ATTbf, g_ATTbf);
    cudaGetSymbolAddress((void**)&Wt,    g_Wt);
    __nv_bfloat16* Wtq = Wt;
    __nv_bfloat16* Wtk = Wt + 65536;
    __nv_bfloat16* Wtv = Wt + 2 * 65536;
    __nv_bfloat16* Wtr = Wt + 3 * 65536;

    cudaFuncSetAttribute(hmma_gemm_kernel,
                         cudaFuncAttributeMaxDynamicSharedMemorySize, GEMM_SMEM);

    cvt_bf16_kernel<<<2048, 256>>>(kf, Kbf);                               // 1
    cvt_bf16_kernel<<<2048, 256>>>(qf, Qbf);                               // 2
    cvt_vw_kernel<<<2112, 256>>>(vf, Vbf, Wq, Wk, Wv, Wr);                 // 3

    // fused Q/K/V projections: proj = blockIdx.z >> 3
    dim3 fused_grid(LD / 128, CD / 128, 3 * NB);
    hmma_gemm_kernel<<<fused_grid, 256, GEMM_SMEM>>>(                      // 4 (ncu)
        Kbf, Qbf, Vbf, Wtk, Wtq, Wtv, bk, bq, bv, K, Q, V, nullptr);

    kstats_kernel<<<NB * CD, 256>>>();                                     // 5
    zero_ctx_kernel<<<(NB * NHEADS * HC * HC) / 256, 256>>>();             // 6
    context_kernel<<<dim3(10, NHEADS, NB), 256>>>();                       // 7
    attend_kernel<<<dim3(LD / 128, NHEADS, NB), 128>>>();                  // 8

    dim3 gemm_grid(LD / 128, CD / 128, NB);
    hmma_gemm_kernel<<<gemm_grid, 256, GEMM_SMEM>>>(                       // 9
        ATTbf, ATTbf, ATTbf, Wtr, Wtr, Wtr, br, br, br, out, out, out, qf);
}

// round 10
// speedup vs baseline: 2.9313x; 1.1239x over previous
#include <cuda_runtime.h>
#include <cuda_bf16.h>
#include <cstdint>

#define NB 8
#define CD 256
#define LD 6400
#define NHEADS 8
#define HC 32

// Scratch (device globals -- no allocation allowed)
__device__ float g_Q[NB * CD * LD];
__device__ float g_K[NB * CD * LD];
__device__ float g_V[NB * CD * LD];
__device__ float g_CTX[NB * NHEADS * HC * HC];
__device__ float g_ksum[NB * CD];
__device__ __nv_bfloat16 g_Qbf[NB * CD * LD];
__device__ __nv_bfloat16 g_Kbf[NB * CD * LD];
__device__ __nv_bfloat16 g_Vbf[NB * CD * LD];
__device__ __nv_bfloat16 g_ATTbf[NB * CD * LD];
__device__ __nv_bfloat16 g_Wt[4 * 256 * 256];   // k-major bf16: Wq,Wk,Wv,Wr

// ---------------------------------------------------------------------------
// mma.sync / ldmatrix / cp.async helpers (baseline PTX, works on compute_103)
// ---------------------------------------------------------------------------
__device__ __forceinline__ uint32_t smem_u32(const void* p) {
    uint32_t a;
    asm("{ .reg .u64 t; cvta.to.shared.u64 t, %1; cvt.u32.u64 %0, t; }"
        : "=r"(a) : "l"(p));
    return a;
}

__device__ __forceinline__ void ldsm4t(uint32_t* r, uint32_t addr) {
    asm volatile("ldmatrix.sync.aligned.m8n8.x4.trans.shared.b16 {%0,%1,%2,%3}, [%4];"
                 : "=r"(r[0]), "=r"(r[1]), "=r"(r[2]), "=r"(r[3]) : "r"(addr));
}

__device__ __forceinline__ void mma16816(float* c, uint32_t a0, uint32_t a1,
                                         uint32_t a2, uint32_t a3,
                                         uint32_t b0, uint32_t b1) {
    asm volatile(
        "mma.sync.aligned.m16n8k16.row.col.f32.bf16.bf16.f32 "
        "{%0,%1,%2,%3}, {%4,%5,%6,%7}, {%8,%9}, {%0,%1,%2,%3};"
        : "+f"(c[0]), "+f"(c[1]), "+f"(c[2]), "+f"(c[3])
        : "r"(a0), "r"(a1), "r"(a2), "r"(a3), "r"(b0), "r"(b1));
}

__device__ __forceinline__ void cpasync16(uint32_t saddr, const void* g) {
    asm volatile("cp.async.cg.shared.global [%0], [%1], 16;"
                 :: "r"(saddr), "l"(g) : "memory");
}
__device__ __forceinline__ void cpasync_commit() {
    asm volatile("cp.async.commit_group;" ::: "memory");
}
__device__ __forceinline__ void cpasync_wait0() {
    asm volatile("cp.async.wait_group 0;" ::: "memory");
}
__device__ __forceinline__ void cpasync_wait1() {
    asm volatile("cp.async.wait_group 1;" ::: "memory");
}

// ---------------------------------------------------------------------------
// Fused conversion: q/k/v fp32 -> bf16 (MLP=4 batched) + 4x W transpose.
// grid (3200, 4): y in {0,1,2} = tensor streams, y==3 & x<64 = W transpose.
// ---------------------------------------------------------------------------
#define CVT_STRIDE 819200   // (NB*CD*LD/4) / 4 float4s per j-slice

__global__ __launch_bounds__(256) void cvt_all_kernel(
    const float* __restrict__ qf, const float* __restrict__ kf,
    const float* __restrict__ vf,
    const float* __restrict__ Wq, const float* __restrict__ Wk,
    const float* __restrict__ Wv, const float* __restrict__ Wr)
{
    const int y = blockIdx.y;
    if (y < 3) {
        const float* src = (y == 0) ? kf : (y == 1) ? qf : vf;
        __nv_bfloat16* dst = (y == 0) ? g_Kbf : (y == 1) ? g_Qbf : g_Vbf;
        const float4* s4 = (const float4*)src;
        const size_t base = (size_t)blockIdx.x * 256 + threadIdx.x;
        float4 v[4];
#pragma unroll
        for (int j = 0; j < 4; ++j) v[j] = s4[base + (size_t)j * CVT_STRIDE];
#pragma unroll
        for (int j = 0; j < 4; ++j) {
            union { __nv_bfloat162 h[2]; unsigned long long u; } u;
            u.h[0] = __float22bfloat162_rn(make_float2(v[j].x, v[j].y));
            u.h[1] = __float22bfloat162_rn(make_float2(v[j].z, v[j].w));
            *(unsigned long long*)&dst[(base + (size_t)j * CVT_STRIDE) * 4] = u.u;
        }
    } else {
        if (blockIdx.x >= 64) return;
        int t = blockIdx.x * 256 + threadIdx.x;   // 0..16383
        const float* Ws[4] = {Wq, Wk, Wv, Wr};
#pragma unroll
        for (int w = 0; w < 4; ++w) {
            const float* W = Ws[w];
            __nv_bfloat16* D = g_Wt + w * 65536;
            for (int idx = t; idx < 65536; idx += 16384) {
                int m = idx >> 8, k = idx & 255;
                D[k * 256 + m] = __float2bfloat16(W[idx]);   // W[m*256+k]
            }
        }
    }
}

// ---------------------------------------------------------------------------
// Zero g_CTX and g_ksum.
// ---------------------------------------------------------------------------
__global__ void zero_kernel()
{
    int i = blockIdx.x * 256 + threadIdx.x;
    if (i < NB * NHEADS * HC * HC) g_CTX[i] = 0.0f;
    int j = i - NB * NHEADS * HC * HC;
    if (j >= 0 && j < NB * CD) g_ksum[j] = 0.0f;
}

// ---------------------------------------------------------------------------
// HMMA GEMM: Y[n, m, l] = sum_k Wt[k,m] * Xbf[n,k,l] + bias[m] (+ resid)
// Block tile 128(m) x 128(l), BK=32, 8 warps (warp tile 32x64).
// cp.async direct bf16, ldsm4t both operands, 3-stage pipeline.
// Fused Q/K/V via blockIdx.z (proj = z>>3).
// ---------------------------------------------------------------------------
#define SB 136                     // bf16 row stride (272B, conflict-free ldsm)
#define REG_EL (32 * SB)           // 4352 bf16 per operand region
#define STAGE_BYTES (2 * REG_EL * 2)   // A + B regions = 17408 bytes
#define GEMM_SMEM (3 * STAGE_BYTES)    // 52224 bytes

__global__ __launch_bounds__(256, 2) void hmma_gemm_kernel(
    const __nv_bfloat16* __restrict__ X0, const __nv_bfloat16* __restrict__ X1,
    const __nv_bfloat16* __restrict__ X2,
    const __nv_bfloat16* __restrict__ Wt0, const __nv_bfloat16* __restrict__ Wt1,
    const __nv_bfloat16* __restrict__ Wt2,
    const float* __restrict__ b0p, const float* __restrict__ b1p,
    const float* __restrict__ b2p,
    float* __restrict__ Y0, float* __restrict__ Y1, float* __restrict__ Y2,
    const float* __restrict__ resid)
{
    extern __shared__ __align__(16) __nv_bfloat16 dsm[];

    const int tid  = threadIdx.x;
    const int wid  = tid >> 5;
    const int lane = tid & 31;
    const int l0   = blockIdx.x * 128;
    const int m0   = blockIdx.y * 128;
    const int proj = blockIdx.z >> 3;
    const int nb   = blockIdx.z & 7;

    const __nv_bfloat16* X;
    const __nv_bfloat16* Wt;
    const float* bias;
    float* Y;
    if (proj == 0)      { X = X0; Wt = Wt0; bias = b0p; Y = Y0; }
    else if (proj == 1) { X = X1; Wt = Wt1; bias = b1p; Y = Y1; }
    else                { X = X2; Wt = Wt2; bias = b2p; Y = Y2; }

    const int m0w = (wid & 3) * 32;   // warp m offset in block
    const int n0w = (wid >> 2) * 64;  // warp n offset in block

    const __nv_bfloat16* Xn = X + (size_t)nb * CD * LD;
    float* Yn = Y + (size_t)nb * CD * LD;
    const float* Rn = resid ? resid + (size_t)nb * CD * LD : nullptr;

    float acc[2][8][4];
#pragma unroll
    for (int i = 0; i < 2; i++)
#pragma unroll
        for (int j = 0; j < 8; j++)
#pragma unroll
            for (int e = 0; e < 4; e++) acc[i][j][e] = 0.0f;

    const uint32_t smBase = smem_u32(dsm);
    const uint32_t chunk = (uint32_t)((tid >> 4) * (SB * 2) + (tid & 15) * 16);
    const uint32_t aOff = (uint32_t)((lane & 15) * (SB * 2) +
                                     (m0w + ((lane >> 4) << 3)) * 2);
    const uint32_t bOff = (uint32_t)((lane & 15) * (SB * 2) +
                                     (n0w + ((lane >> 4) << 3)) * 2);
    const int g_k  = tid >> 4;    // 0..15
    const int g_c8 = (tid & 15) * 8;

#define ISSUE(c)                                                               \
    {                                                                          \
        uint32_t sb = smBase + ((c) % 3) * STAGE_BYTES;                        \
        const __nv_bfloat16* gA = Wt + ((c) * 32 + g_k) * 256 + m0 + g_c8;     \
        cpasync16(sb + chunk, gA);                                             \
        cpasync16(sb + chunk + 16 * SB * 2, gA + 16 * 256);                    \
        const __nv_bfloat16* gB =                                              \
            Xn + (size_t)((c) * 32 + g_k) * LD + l0 + g_c8;                    \
        cpasync16(sb + 2 * REG_EL + chunk, gB);                                \
        cpasync16(sb + 2 * REG_EL + chunk + 16 * SB * 2, gB + (size_t)16 * LD);\
        cpasync_commit();                                                      \
    }

    ISSUE(0);
    ISSUE(1);

#pragma unroll
    for (int c = 0; c < 8; ++c) {
        if (c < 7) cpasync_wait1(); else cpasync_wait0();
        __syncthreads();
        if (c < 6) ISSUE(c + 2);

        uint32_t aA = smBase + (c % 3) * STAGE_BYTES + aOff;
        uint32_t bA = aA - aOff + 2 * REG_EL + bOff;
#pragma unroll
        for (int ks = 0; ks < 2; ++ks) {
            uint32_t a4[2][4];
#pragma unroll
            for (int im = 0; im < 2; ++im)
                ldsm4t(a4[im], aA + (uint32_t)(ks * 16 * SB * 2 + im * 32));
#pragma unroll
            for (int jp = 0; jp < 4; ++jp) {
                uint32_t b4[4];
                ldsm4t(b4, bA + (uint32_t)(ks * 16 * SB * 2 + jp * 32));
#pragma unroll
                for (int im = 0; im < 2; ++im) {
                    // A fragment from transposed ldsm: {r0, r2, r1, r3}
                    mma16816(acc[im][jp * 2 + 0], a4[im][0], a4[im][2],
                             a4[im][1], a4[im][3], b4[0], b4[1]);
                    mma16816(acc[im][jp * 2 + 1], a4[im][0], a4[im][2],
                             a4[im][1], a4[im][3], b4[2], b4[3]);
                }
            }
        }
    }

    // ---- epilogue: regs -> global, + bias (+ residual)
    const int qr = lane >> 2;        // 0..7
    const int qc = (lane & 3) * 2;   // 0,2,4,6
#pragma unroll
    for (int im = 0; im < 2; ++im) {
        int mA = m0 + m0w + im * 16 + qr;
        int mB = mA + 8;
        float bA = bias[mA];
        float bB = bias[mB];
#pragma unroll
        for (int jn = 0; jn < 8; ++jn) {
            int n = l0 + n0w + jn * 8 + qc;
            size_t gA = (size_t)mA * LD + n;
            size_t gB = (size_t)mB * LD + n;
            float o0 = acc[im][jn][0] + bA;
            float o1 = acc[im][jn][1] + bA;
            float o2 = acc[im][jn][2] + bB;
            float o3 = acc[im][jn][3] + bB;
            if (Rn) {
                float2 rA = *(const float2*)(Rn + gA);
                float2 rB = *(const float2*)(Rn + gB);
                o0 += rA.x; o1 += rA.y; o2 += rB.x; o3 += rB.y;
            }
            float2 vA = {o0, o1};
            float2 vB = {o2, o3};
            *(float2*)(Yn + gA) = vA;
            *(float2*)(Yn + gB) = vB;
        }
    }
}

// ---------------------------------------------------------------------------
// context[n,h,kc,vc] = sum_l exp(K[n,h,kc,l]) * V[n,h,vc,l]   (unnormalized)
// Also accumulates g_ksum[row] = sum_l exp(K[row][l]) via atomics.
// (No max subtraction: |K| <~ 7 so exp is fp32-safe; matches reference
//  softmax exactly up to fp rounding.)
// ---------------------------------------------------------------------------
__global__ __launch_bounds__(256) void context_kernel()
{
    __shared__ float sk[32][129];
    __shared__ float sv[32][129];
    const int n = blockIdx.z, h = blockIdx.y;
    const size_t base = (((size_t)n * NHEADS + h) * HC) * LD;
    const int rowbase = n * CD + h * HC;
    const int tid = threadIdx.x;
    const int kc = tid >> 3;
    const int sub = tid & 7;
    const int vg = sub * 4;

    float acc0 = 0.f, acc1 = 0.f, acc2 = 0.f, acc3 = 0.f;
    float ksum_acc = 0.f;

    for (int t = 0; t < 5; ++t) {
        const int l0 = blockIdx.x * 640 + t * 128;
#pragma unroll
        for (int s = 0; s < 16; s++) {
            int idx = tid + s * 256;
            int c = idx >> 7, l = idx & 127;
            sk[c][l] = __expf(g_K[base + (size_t)c * LD + l0 + l]);
            sv[c][l] = g_V[base + (size_t)c * LD + l0 + l];
        }
        __syncthreads();
        // per-row exp sums (this thread: row kc, columns sub*16..sub*16+15)
        {
            float s = 0.f;
#pragma unroll
            for (int j = 0; j < 16; ++j) s += sk[kc][sub * 16 + j];
            ksum_acc += s;
        }
#pragma unroll 4
        for (int l = 0; l < 128; l++) {
            float a = sk[kc][l];
            acc0 += a * sv[vg + 0][l];
            acc1 += a * sv[vg + 1][l];
            acc2 += a * sv[vg + 2][l];
            acc3 += a * sv[vg + 3][l];
        }
        __syncthreads();
    }
    atomicAdd(&g_ksum[rowbase + kc], ksum_acc);
    const size_t cb = (((size_t)n * NHEADS + h) * HC + kc) * HC + vg;
    atomicAdd(&g_CTX[cb + 0], acc0);
    atomicAdd(&g_CTX[cb + 1], acc1);
    atomicAdd(&g_CTX[cb + 2], acc2);
    atomicAdd(&g_CTX[cb + 3], acc3);
}

// ---------------------------------------------------------------------------
// attended[n,h,vc,l] = sum_kc (ctx[n,h,kc,vc]/ksum[kc]) * softmax_C(q)[n,h,kc,l]
// Writes bf16 directly for the recovery GEMM.
// ---------------------------------------------------------------------------
__global__ __launch_bounds__(128) void attend_kernel()
{
    __shared__ float4 sctx[32][8];
    const int n = blockIdx.z, h = blockIdx.y;
    const int tid = threadIdx.x;
    const int rowbase = n * CD + h * HC;
    {
        const float4* C = (const float4*)(g_CTX + (((size_t)n * NHEADS + h) * HC) * HC);
#pragma unroll
        for (int s = 0; s < 2; s++) {
            int idx = tid + s * 128;
            float inv = 1.0f / g_ksum[rowbase + (idx >> 3)];
            float4 v = C[idx];
            v.x *= inv; v.y *= inv; v.z *= inv; v.w *= inv;
            sctx[idx >> 3][idx & 7] = v;
        }
    }
    __syncthreads();

    const int l = blockIdx.x * 128 + tid;
    const size_t base = (((size_t)n * NHEADS + h) * HC) * LD + l;

    float q[HC];
    float mx = -1e30f;
#pragma unroll
    for (int c = 0; c < HC; c++) {
        q[c] = g_Q[base + (size_t)c * LD];
        mx = fmaxf(mx, q[c]);
    }
    float s = 0.0f;
#pragma unroll
    for (int c = 0; c < HC; c++) {
        q[c] = __expf(q[c] - mx);
        s += q[c];
    }
    float inv = 1.0f / s;
#pragma unroll
    for (int c = 0; c < HC; c++) q[c] *= inv;

    float acc[HC];
#pragma unroll
    for (int v = 0; v < HC; v++) acc[v] = 0.0f;

#pragma unroll
    for (int kc = 0; kc < HC; kc++) {
        float a = q[kc];
#pragma unroll
        for (int vq = 0; vq < 8; vq++) {
            float4 c4 = sctx[kc][vq];
            acc[vq * 4 + 0] += a * c4.x;
            acc[vq * 4 + 1] += a * c4.y;
            acc[vq * 4 + 2] += a * c4.z;
            acc[vq * 4 + 3] += a * c4.w;
        }
    }
#pragma unroll
    for (int v = 0; v < HC; v++)
        g_ATTbf[base + (size_t)v * LD] = __float2bfloat16(acc[v]);
}

// ---------------------------------------------------------------------------
extern "C" void kernel_launch(void* const* d_in, const int* in_sizes, int n_in,
                              void* d_out, int out_size)
{
    const float* qf = (const float*)d_in[0];
    const float* kf = (const float*)d_in[1];
    const float* vf = (const float*)d_in[2];
    const float* Wq = (const float*)d_in[3];
    const float* bq = (const float*)d_in[4];
    const float* Wk = (const float*)d_in[5];
    const float* bk = (const float*)d_in[6];
    const float* Wv = (const float*)d_in[7];
    const float* bv = (const float*)d_in[8];
    const float* Wr = (const float*)d_in[9];
    const float* br = (const float*)d_in[10];
    float* out = (float*)d_out;

    float *Q, *K, *V;
    __nv_bfloat16 *Qbf, *Kbf, *Vbf, *ATTbf, *Wt;
    cudaGetSymbolAddress((void**)&Q,     g_Q);
    cudaGetSymbolAddress((void**)&K,     g_K);
    cudaGetSymbolAddress((void**)&V,     g_V);
    cudaGetSymbolAddress((void**)&Qbf,   g_Qbf);
    cudaGetSymbolAddress((void**)&Kbf,   g_Kbf);
    cudaGetSymbolAddress((void**)&Vbf,   g_Vbf);
    cudaGetSymbolAddress((void**)&ATTbf, g_ATTbf);
    cudaGetSymbolAddress((void**)&Wt,    g_Wt);
    __nv_bfloat16* Wtq = Wt;
    __nv_bfloat16* Wtk = Wt + 65536;
    __nv_bfloat16* Wtv = Wt + 2 * 65536;
    __nv_bfloat16* Wtr = Wt + 3 * 65536;

    cudaFuncSetAttribute(hmma_gemm_kernel,
                         cudaFuncAttributeMaxDynamicSharedMemorySize, GEMM_SMEM);

    cvt_all_kernel<<<dim3(3200, 4), 256>>>(qf, kf, vf, Wq, Wk, Wv, Wr);    // 1
    zero_kernel<<<264, 256>>>();                                           // 2

    // fused Q/K/V projections: proj = blockIdx.z >> 3
    dim3 fused_grid(LD / 128, CD / 128, 3 * NB);
    hmma_gemm_kernel<<<fused_grid, 256, GEMM_SMEM>>>(                      // 3
        Kbf, Qbf, Vbf, Wtk, Wtq, Wtv, bk, bq, bv, K, Q, V, nullptr);

    context_kernel<<<dim3(10, NHEADS, NB), 256>>>();                       // 4
    attend_kernel<<<dim3(LD / 128, NHEADS, NB), 128>>>();                  // 5

    dim3 gemm_grid(LD / 128, CD / 128, NB);
    hmma_gemm_kernel<<<gemm_grid, 256, GEMM_SMEM>>>(                       // 6 (ncu)
        ATTbf, ATTbf, ATTbf, Wtr, Wtr, Wtr, br, br, br, out, out, out, qf);
}

// round 11
// speedup vs baseline: 3.1546x; 1.0762x over previous
#include <cuda_runtime.h>
#include <cuda_bf16.h>
#include <cstdint>

#define NB 8
#define CD 256
#define LD 6400
#define NHEADS 8
#define HC 32

// Scratch (device globals -- no allocation allowed)
__device__ float g_Q[NB * CD * LD];
__device__ float g_K[NB * CD * LD];
__device__ float g_V[NB * CD * LD];
__device__ float g_CTX[NB * NHEADS * HC * HC];
__device__ float g_ksum[NB * CD];
__device__ __nv_bfloat16 g_Qbf[NB * CD * LD];
__device__ __nv_bfloat16 g_Kbf[NB * CD * LD];
__device__ __nv_bfloat16 g_Vbf[NB * CD * LD];
__device__ __nv_bfloat16 g_ATTbf[NB * CD * LD];
__device__ __nv_bfloat16 g_Wt[4 * 256 * 256];   // k-major bf16: Wq,Wk,Wv,Wr

// ---------------------------------------------------------------------------
// mma.sync / ldmatrix / cp.async helpers (baseline PTX, works on compute_103)
// ---------------------------------------------------------------------------
__device__ __forceinline__ uint32_t smem_u32(const void* p) {
    uint32_t a;
    asm("{ .reg .u64 t; cvta.to.shared.u64 t, %1; cvt.u32.u64 %0, t; }"
        : "=r"(a) : "l"(p));
    return a;
}

__device__ __forceinline__ void ldsm4t(uint32_t* r, uint32_t addr) {
    asm volatile("ldmatrix.sync.aligned.m8n8.x4.trans.shared.b16 {%0,%1,%2,%3}, [%4];"
                 : "=r"(r[0]), "=r"(r[1]), "=r"(r[2]), "=r"(r[3]) : "r"(addr));
}

__device__ __forceinline__ void mma16816(float* c, uint32_t a0, uint32_t a1,
                                         uint32_t a2, uint32_t a3,
                                         uint32_t b0, uint32_t b1) {
    asm volatile(
        "mma.sync.aligned.m16n8k16.row.col.f32.bf16.bf16.f32 "
        "{%0,%1,%2,%3}, {%4,%5,%6,%7}, {%8,%9}, {%0,%1,%2,%3};"
        : "+f"(c[0]), "+f"(c[1]), "+f"(c[2]), "+f"(c[3])
        : "r"(a0), "r"(a1), "r"(a2), "r"(a3), "r"(b0), "r"(b1));
}

__device__ __forceinline__ void cpasync16(uint32_t saddr, const void* g) {
    asm volatile("cp.async.cg.shared.global [%0], [%1], 16;"
                 :: "r"(saddr), "l"(g) : "memory");
}
__device__ __forceinline__ void cpasync_commit() {
    asm volatile("cp.async.commit_group;" ::: "memory");
}
__device__ __forceinline__ void cpasync_wait0() {
    asm volatile("cp.async.wait_group 0;" ::: "memory");
}
__device__ __forceinline__ void cpasync_wait1() {
    asm volatile("cp.async.wait_group 1;" ::: "memory");
}

// ---------------------------------------------------------------------------
// Fused conversion: q/k/v fp32 -> bf16 (MLP=4 batched) + 4x W transpose.
// grid (3200, 4): y in {0,1,2} = tensor streams, y==3 & x<64 = W transpose.
// ---------------------------------------------------------------------------
#define CVT_STRIDE 819200   // (NB*CD*LD/4) / 4 float4s per j-slice

__global__ __launch_bounds__(256) void cvt_all_kernel(
    const float* __restrict__ qf, const float* __restrict__ kf,
    const float* __restrict__ vf,
    const float* __restrict__ Wq, const float* __restrict__ Wk,
    const float* __restrict__ Wv, const float* __restrict__ Wr)
{
    const int y = blockIdx.y;
    if (y < 3) {
        const float* src = (y == 0) ? kf : (y == 1) ? qf : vf;
        __nv_bfloat16* dst = (y == 0) ? g_Kbf : (y == 1) ? g_Qbf : g_Vbf;
        const float4* s4 = (const float4*)src;
        const size_t base = (size_t)blockIdx.x * 256 + threadIdx.x;
        float4 v[4];
#pragma unroll
        for (int j = 0; j < 4; ++j) v[j] = s4[base + (size_t)j * CVT_STRIDE];
#pragma unroll
        for (int j = 0; j < 4; ++j) {
            union { __nv_bfloat162 h[2]; unsigned long long u; } u;
            u.h[0] = __float22bfloat162_rn(make_float2(v[j].x, v[j].y));
            u.h[1] = __float22bfloat162_rn(make_float2(v[j].z, v[j].w));
            *(unsigned long long*)&dst[(base + (size_t)j * CVT_STRIDE) * 4] = u.u;
        }
    } else {
        if (blockIdx.x >= 64) return;
        int t = blockIdx.x * 256 + threadIdx.x;   // 0..16383
        const float* Ws[4] = {Wq, Wk, Wv, Wr};
#pragma unroll
        for (int w = 0; w < 4; ++w) {
            const float* W = Ws[w];
            __nv_bfloat16* D = g_Wt + w * 65536;
            for (int idx = t; idx < 65536; idx += 16384) {
                int m = idx >> 8, k = idx & 255;
                D[k * 256 + m] = __float2bfloat16(W[idx]);   // W[m*256+k]
            }
        }
    }
}

// ---------------------------------------------------------------------------
// Zero g_CTX and g_ksum.
// ---------------------------------------------------------------------------
__global__ void zero_kernel()
{
    int i = blockIdx.x * 256 + threadIdx.x;
    if (i < NB * NHEADS * HC * HC) g_CTX[i] = 0.0f;
    int j = i - NB * NHEADS * HC * HC;
    if (j >= 0 && j < NB * CD) g_ksum[j] = 0.0f;
}

// ---------------------------------------------------------------------------
// HMMA GEMM: Y[n, m, l] = sum_k Wt[k,m] * Xbf[n,k,l] + bias[m] (+ resid)
// Block tile 128(m) x 128(l), BK=32, 8 warps (warp tile 32x64).
// cp.async direct bf16, ldsm4t both operands, 3-stage pipeline.
// Fused Q/K/V via blockIdx.z (proj = z>>3).
// ---------------------------------------------------------------------------
#define SB 136                     // bf16 row stride (272B, conflict-free ldsm)
#define REG_EL (32 * SB)           // 4352 bf16 per operand region
#define STAGE_BYTES (2 * REG_EL * 2)   // A + B regions = 17408 bytes
#define GEMM_SMEM (3 * STAGE_BYTES)    // 52224 bytes

__global__ __launch_bounds__(256, 2) void hmma_gemm_kernel(
    const __nv_bfloat16* __restrict__ X0, const __nv_bfloat16* __restrict__ X1,
    const __nv_bfloat16* __restrict__ X2,
    const __nv_bfloat16* __restrict__ Wt0, const __nv_bfloat16* __restrict__ Wt1,
    const __nv_bfloat16* __restrict__ Wt2,
    const float* __restrict__ b0p, const float* __restrict__ b1p,
    const float* __restrict__ b2p,
    float* __restrict__ Y0, float* __restrict__ Y1, float* __restrict__ Y2,
    const float* __restrict__ resid)
{
    extern __shared__ __align__(16) __nv_bfloat16 dsm[];

    const int tid  = threadIdx.x;
    const int wid  = tid >> 5;
    const int lane = tid & 31;
    const int l0   = blockIdx.x * 128;
    const int m0   = blockIdx.y * 128;
    const int proj = blockIdx.z >> 3;
    const int nb   = blockIdx.z & 7;

    const __nv_bfloat16* X;
    const __nv_bfloat16* Wt;
    const float* bias;
    float* Y;
    if (proj == 0)      { X = X0; Wt = Wt0; bias = b0p; Y = Y0; }
    else if (proj == 1) { X = X1; Wt = Wt1; bias = b1p; Y = Y1; }
    else                { X = X2; Wt = Wt2; bias = b2p; Y = Y2; }

    const int m0w = (wid & 3) * 32;   // warp m offset in block
    const int n0w = (wid >> 2) * 64;  // warp n offset in block

    const __nv_bfloat16* Xn = X + (size_t)nb * CD * LD;
    float* Yn = Y + (size_t)nb * CD * LD;
    const float* Rn = resid ? resid + (size_t)nb * CD * LD : nullptr;

    float acc[2][8][4];
#pragma unroll
    for (int i = 0; i < 2; i++)
#pragma unroll
        for (int j = 0; j < 8; j++)
#pragma unroll
            for (int e = 0; e < 4; e++) acc[i][j][e] = 0.0f;

    const uint32_t smBase = smem_u32(dsm);
    const uint32_t chunk = (uint32_t)((tid >> 4) * (SB * 2) + (tid & 15) * 16);
    const uint32_t aOff = (uint32_t)((lane & 15) * (SB * 2) +
                                     (m0w + ((lane >> 4) << 3)) * 2);
    const uint32_t bOff = (uint32_t)((lane & 15) * (SB * 2) +
                                     (n0w + ((lane >> 4) << 3)) * 2);
    const int g_k  = tid >> 4;    // 0..15
    const int g_c8 = (tid & 15) * 8;

#define ISSUE(c)                                                               \
    {                                                                          \
        uint32_t sb = smBase + ((c) % 3) * STAGE_BYTES;                        \
        const __nv_bfloat16* gA = Wt + ((c) * 32 + g_k) * 256 + m0 + g_c8;     \
        cpasync16(sb + chunk, gA);                                             \
        cpasync16(sb + chunk + 16 * SB * 2, gA + 16 * 256);                    \
        const __nv_bfloat16* gB =                                              \
            Xn + (size_t)((c) * 32 + g_k) * LD + l0 + g_c8;                    \
        cpasync16(sb + 2 * REG_EL + chunk, gB);                                \
        cpasync16(sb + 2 * REG_EL + chunk + 16 * SB * 2, gB + (size_t)16 * LD);\
        cpasync_commit();                                                      \
    }

    ISSUE(0);
    ISSUE(1);

#pragma unroll
    for (int c = 0; c < 8; ++c) {
        if (c < 7) cpasync_wait1(); else cpasync_wait0();
        __syncthreads();
        if (c < 6) ISSUE(c + 2);

        uint32_t aA = smBase + (c % 3) * STAGE_BYTES + aOff;
        uint32_t bA = aA - aOff + 2 * REG_EL + bOff;
#pragma unroll
        for (int ks = 0; ks < 2; ++ks) {
            uint32_t a4[2][4];
#pragma unroll
            for (int im = 0; im < 2; ++im)
                ldsm4t(a4[im], aA + (uint32_t)(ks * 16 * SB * 2 + im * 32));
#pragma unroll
            for (int jp = 0; jp < 4; ++jp) {
                uint32_t b4[4];
                ldsm4t(b4, bA + (uint32_t)(ks * 16 * SB * 2 + jp * 32));
#pragma unroll
                for (int im = 0; im < 2; ++im) {
                    // A fragment from transposed ldsm: {r0, r2, r1, r3}
                    mma16816(acc[im][jp * 2 + 0], a4[im][0], a4[im][2],
                             a4[im][1], a4[im][3], b4[0], b4[1]);
                    mma16816(acc[im][jp * 2 + 1], a4[im][0], a4[im][2],
                             a4[im][1], a4[im][3], b4[2], b4[3]);
                }
            }
        }
    }

    // ---- epilogue: regs -> global, + bias (+ residual)
    const int qr = lane >> 2;        // 0..7
    const int qc = (lane & 3) * 2;   // 0,2,4,6
#pragma unroll
    for (int im = 0; im < 2; ++im) {
        int mA = m0 + m0w + im * 16 + qr;
        int mB = mA + 8;
        float bA = bias[mA];
        float bB = bias[mB];
#pragma unroll
        for (int jn = 0; jn < 8; ++jn) {
            int n = l0 + n0w + jn * 8 + qc;
            size_t gA = (size_t)mA * LD + n;
            size_t gB = (size_t)mB * LD + n;
            float o0 = acc[im][jn][0] + bA;
            float o1 = acc[im][jn][1] + bA;
            float o2 = acc[im][jn][2] + bB;
            float o3 = acc[im][jn][3] + bB;
            if (Rn) {
                float2 rA = *(const float2*)(Rn + gA);
                float2 rB = *(const float2*)(Rn + gB);
                o0 += rA.x; o1 += rA.y; o2 += rB.x; o3 += rB.y;
            }
            float2 vA = {o0, o1};
            float2 vB = {o2, o3};
            *(float2*)(Yn + gA) = vA;
            *(float2*)(Yn + gB) = vB;
        }
    }
}

// ---------------------------------------------------------------------------
// context[n,h,kc,vc] = sum_l exp(K[n,h,kc,l]) * V[n,h,vc,l]   (unnormalized)
// Register-tiled: l-major smem staging, each thread owns a 4kc x 4vc tile
// (2x LDS.128 per l for 16 FMA -> 2 B/FMA smem traffic).
// Also accumulates g_ksum[row] = sum_l exp(K[row][l]) via vcg==0 threads.
// ---------------------------------------------------------------------------
#define CPAD 36   // floats per l-row (16B aligned, conflict-free fp4 reads)

__global__ __launch_bounds__(256) void context_kernel()
{
    __shared__ float skT[128][CPAD];
    __shared__ float svT[128][CPAD];
    const int n = blockIdx.z, h = blockIdx.y;
    const size_t base = (((size_t)n * NHEADS + h) * HC) * LD;
    const int rowbase = n * CD + h * HC;
    const int tid = threadIdx.x;
    const int grp = tid >> 6;        // 0..3 (l sub-range within 128-tile)
    const int t64 = tid & 63;
    const int kc0 = (t64 >> 3) * 4;  // 0,4,..,28
    const int vc0 = (t64 & 7) * 4;   // 0,4,..,28
    const bool do_ksum = ((t64 & 7) == 0);

    float acc[4][4];
#pragma unroll
    for (int i = 0; i < 4; ++i)
#pragma unroll
        for (int j = 0; j < 4; ++j) acc[i][j] = 0.0f;
    float ks[4] = {0.f, 0.f, 0.f, 0.f};

    for (int t = 0; t < 5; ++t) {
        const int l0 = blockIdx.x * 640 + t * 128;
#pragma unroll
        for (int s = 0; s < 16; s++) {
            int idx = tid + s * 256;
            int c = idx >> 7, l = idx & 127;
            skT[l][c] = __expf(g_K[base + (size_t)c * LD + l0 + l]);
            svT[l][c] = g_V[base + (size_t)c * LD + l0 + l];
        }
        __syncthreads();
#pragma unroll 4
        for (int li = 0; li < 32; ++li) {
            int l = grp * 32 + li;
            float4 a4 = *(const float4*)&skT[l][kc0];
            float4 b4 = *(const float4*)&svT[l][vc0];
            float a[4] = {a4.x, a4.y, a4.z, a4.w};
            float b[4] = {b4.x, b4.y, b4.z, b4.w};
#pragma unroll
            for (int i = 0; i < 4; ++i)
#pragma unroll
                for (int j = 0; j < 4; ++j)
                    acc[i][j] += a[i] * b[j];
            if (do_ksum) {
                ks[0] += a[0]; ks[1] += a[1]; ks[2] += a[2]; ks[3] += a[3];
            }
        }
        __syncthreads();
    }

    if (do_ksum) {
#pragma unroll
        for (int i = 0; i < 4; ++i)
            atomicAdd(&g_ksum[rowbase + kc0 + i], ks[i]);
    }
    float* C = g_CTX + (((size_t)n * NHEADS + h) * HC) * HC;
#pragma unroll
    for (int i = 0; i < 4; ++i)
#pragma unroll
        for (int j = 0; j < 4; ++j)
            atomicAdd(&C[(kc0 + i) * HC + vc0 + j], acc[i][j]);
}

// ---------------------------------------------------------------------------
// attended[n,h,vc,l] = sum_kc (ctx[n,h,kc,vc]/ksum[kc]) * softmax_C(q)[n,h,kc,l]
// Writes bf16 directly for the recovery GEMM.
// ---------------------------------------------------------------------------
__global__ __launch_bounds__(128) void attend_kernel()
{
    __shared__ float4 sctx[32][8];
    const int n = blockIdx.z, h = blockIdx.y;
    const int tid = threadIdx.x;
    const int rowbase = n * CD + h * HC;
    {
        const float4* C = (const float4*)(g_CTX + (((size_t)n * NHEADS + h) * HC) * HC);
#pragma unroll
        for (int s = 0; s < 2; s++) {
            int idx = tid + s * 128;
            float inv = 1.0f / g_ksum[rowbase + (idx >> 3)];
            float4 v = C[idx];
            v.x *= inv; v.y *= inv; v.z *= inv; v.w *= inv;
            sctx[idx >> 3][idx & 7] = v;
        }
    }
    __syncthreads();

    const int l = blockIdx.x * 128 + tid;
    const size_t base = (((size_t)n * NHEADS + h) * HC) * LD + l;

    float q[HC];
    float mx = -1e30f;
#pragma unroll
    for (int c = 0; c < HC; c++) {
        q[c] = g_Q[base + (size_t)c * LD];
        mx = fmaxf(mx, q[c]);
    }
    float s = 0.0f;
#pragma unroll
    for (int c = 0; c < HC; c++) {
        q[c] = __expf(q[c] - mx);
        s += q[c];
    }
    float inv = 1.0f / s;
#pragma unroll
    for (int c = 0; c < HC; c++) q[c] *= inv;

    float acc[HC];
#pragma unroll
    for (int v = 0; v < HC; v++) acc[v] = 0.0f;

#pragma unroll
    for (int kc = 0; kc < HC; kc++) {
        float a = q[kc];
#pragma unroll
        for (int vq = 0; vq < 8; vq++) {
            float4 c4 = sctx[kc][vq];
            acc[vq * 4 + 0] += a * c4.x;
            acc[vq * 4 + 1] += a * c4.y;
            acc[vq * 4 + 2] += a * c4.z;
            acc[vq * 4 + 3] += a * c4.w;
        }
    }
#pragma unroll
    for (int v = 0; v < HC; v++)
        g_ATTbf[base + (size_t)v * LD] = __float2bfloat16(acc[v]);
}

// ---------------------------------------------------------------------------
extern "C" void kernel_launch(void* const* d_in, const int* in_sizes, int n_in,
                              void* d_out, int out_size)
{
    const float* qf = (const float*)d_in[0];
    const float* kf = (const float*)d_in[1];
    const float* vf = (const float*)d_in[2];
    const float* Wq = (const float*)d_in[3];
    const float* bq = (const float*)d_in[4];
    const float* Wk = (const float*)d_in[5];
    const float* bk = (const float*)d_in[6];
    const float* Wv = (const float*)d_in[7];
    const float* bv = (const float*)d_in[8];
    const float* Wr = (const float*)d_in[9];
    const float* br = (const float*)d_in[10];
    float* out = (float*)d_out;

    float *Q, *K, *V;
    __nv_bfloat16 *Qbf, *Kbf, *Vbf, *ATTbf, *Wt;
    cudaGetSymbolAddress((void**)&Q,     g_Q);
    cudaGetSymbolAddress((void**)&K,     g_K);
    cudaGetSymbolAddress((void**)&V,     g_V);
    cudaGetSymbolAddress((void**)&Qbf,   g_Qbf);
    cudaGetSymbolAddress((void**)&Kbf,   g_Kbf);
    cudaGetSymbolAddress((void**)&Vbf,   g_Vbf);
    cudaGetSymbolAddress((void**)&ATTbf, g_ATTbf);
    cudaGetSymbolAddress((void**)&Wt,    g_Wt);
    __nv_bfloat16* Wtq = Wt;
    __nv_bfloat16* Wtk = Wt + 65536;
    __nv_bfloat16* Wtv = Wt + 2 * 65536;
    __nv_bfloat16* Wtr = Wt + 3 * 65536;

    cudaFuncSetAttribute(hmma_gemm_kernel,
                         cudaFuncAttributeMaxDynamicSharedMemorySize, GEMM_SMEM);

    cvt_all_kernel<<<dim3(3200, 4), 256>>>(qf, kf, vf, Wq, Wk, Wv, Wr);    // 1
    zero_kernel<<<264, 256>>>();                                           // 2

    // fused Q/K/V projections: proj = blockIdx.z >> 3
    dim3 fused_grid(LD / 128, CD / 128, 3 * NB);
    hmma_gemm_kernel<<<fused_grid, 256, GEMM_SMEM>>>(                      // 3
        Kbf, Qbf, Vbf, Wtk, Wtq, Wtv, bk, bq, bv, K, Q, V, nullptr);

    context_kernel<<<dim3(10, NHEADS, NB), 256>>>();                       // 4 (ncu)
    attend_kernel<<<dim3(LD / 128, NHEADS, NB), 128>>>();                  // 5

    dim3 gemm_grid(LD / 128, CD / 128, NB);
    hmma_gemm_kernel<<<gemm_grid, 256, GEMM_SMEM>>>(                       // 6
        ATTbf, ATTbf, ATTbf, Wtr, Wtr, Wtr, br, br, br, out, out, out, qf);
}